// round 2
// baseline (speedup 1.0000x reference)
#include <cuda_runtime.h>

#define D 128
#define NSRC 50000
#define NDST 50000
#define NEDGE 640000
#define NEG_SLOPE 0.01f

// ---------------- device scratch (static, no allocation) ----------------
__device__ float g_hs[NSRC * D];
__device__ float g_hd[NDST * D];
__device__ float g_nf[NDST * D];
__device__ float g_score[NEDGE];
__device__ int g_count[NDST];
__device__ int g_offset[NDST + 1];
__device__ int g_cursor[NDST];
__device__ int g_eorder[NEDGE];
__device__ int g_bsums[64];
__device__ int g_bsums2[64];

__device__ __forceinline__ float lrelu(float x) { return x > 0.f ? x : NEG_SLOPE * x; }

// =======================================================================
// Node GEMM: Out[r][n] = act( sum_k A[r][k] * W[k][n] + bias[n] )
// 128-row x 128-col tile per block, 256 threads, fp32x2 packed FMA core.
// A tile is XOR-swizzled in smem so the 8 scalar A reads per k are
// conflict-free alongside the two LDS.128 W reads.
// =======================================================================
__global__ __launch_bounds__(256, 1)
void gemm_node(const float* __restrict__ A, const float* __restrict__ W,
               const float* __restrict__ bias, float* __restrict__ Out,
               int nrows, int act)
{
    extern __shared__ float smem[];
    float* sA = smem;              // 128x128 (swizzled)
    float* sW = smem + 128 * 128;  // 128x128

    const int tid = threadIdx.x;
    const int row0 = blockIdx.x * 128;
    const float4* A4 = (const float4*)A;
    const float4* W4 = (const float4*)W;
    float4* sA4 = (float4*)sA;
    float4* sW4 = (float4*)sW;

#pragma unroll
    for (int it = 0; it < 16; ++it) {
        int idx = it * 256 + tid;
        int r = idx >> 5, c4 = idx & 31;
        int gr = row0 + r;
        float4 v = make_float4(0.f, 0.f, 0.f, 0.f);
        if (gr < nrows) v = A4[gr * 32 + c4];
        sA4[r * 32 + (c4 ^ ((r >> 2) & 7))] = v;
        sW4[idx] = W4[idx];
    }
    __syncthreads();

    const int tx = tid & 15, ty = tid >> 4;
    unsigned long long acc[8][4];
#pragma unroll
    for (int i = 0; i < 8; ++i)
#pragma unroll
        for (int j = 0; j < 4; ++j) acc[i][j] = 0ull;

    const ulonglong2* sw128 = (const ulonglong2*)sW;
    const int swz = (ty & 7) << 2;
    const int rb0 = (ty * 4) * 128;
    const int rb1 = (64 + ty * 4) * 128;

#pragma unroll 4
    for (int k = 0; k < 128; ++k) {
        int ks = k ^ swz;
        float a[8];
#pragma unroll
        for (int i = 0; i < 4; ++i) {
            a[i]     = sA[rb0 + i * 128 + ks];
            a[4 + i] = sA[rb1 + i * 128 + ks];
        }
        ulonglong2 q0 = sw128[k * 32 + tx];
        ulonglong2 q1 = sw128[k * 32 + 16 + tx];
        unsigned long long wp[4] = {q0.x, q0.y, q1.x, q1.y};
        unsigned long long ap[8];
#pragma unroll
        for (int i = 0; i < 8; ++i)
            asm("mov.b64 %0, {%1, %1};" : "=l"(ap[i]) : "f"(a[i]));
#pragma unroll
        for (int i = 0; i < 8; ++i)
#pragma unroll
            for (int j = 0; j < 4; ++j)
                asm("fma.rn.f32x2 %0, %1, %2, %0;"
                    : "+l"(acc[i][j]) : "l"(ap[i]), "l"(wp[j]));
    }

    const float4* b4 = (const float4*)bias;
    float4 bb0 = b4[tx], bb1 = b4[16 + tx];
    float bcol[8] = {bb0.x, bb0.y, bb0.z, bb0.w, bb1.x, bb1.y, bb1.z, bb1.w};
    float4* Out4 = (float4*)Out;
#pragma unroll
    for (int i = 0; i < 8; ++i) {
        int r = (i < 4) ? (ty * 4 + i) : (64 + ty * 4 + i - 4);
        int gr = row0 + r;
        if (gr >= nrows) continue;
        float o[8];
#pragma unroll
        for (int j = 0; j < 4; ++j)
            asm("mov.b64 {%0, %1}, %2;" : "=f"(o[2 * j]), "=f"(o[2 * j + 1]) : "l"(acc[i][j]));
#pragma unroll
        for (int j = 0; j < 8; ++j) {
            o[j] += bcol[j];
            if (act) o[j] = lrelu(o[j]);
        }
        Out4[gr * 32 + tx]      = make_float4(o[0], o[1], o[2], o[3]);
        Out4[gr * 32 + 16 + tx] = make_float4(o[4], o[5], o[6], o[7]);
    }
}

// =======================================================================
// Edge scoring: per 128-edge tile, build T = lrelu(hs[src]+hd[dst]) in
// smem (gathers hit L2), U = T @ W_a1 in registers (same f32x2 core),
// then s = lrelu(U + b_a1) . W_a2 + b_a2 via partial reduction in smem.
// =======================================================================
__global__ __launch_bounds__(256, 1)
void edge_score(const int* __restrict__ src_idx, const int* __restrict__ dst_idx,
                const float* __restrict__ Wa1, const float* __restrict__ ba1,
                const float* __restrict__ Wa2, const float* __restrict__ ba2)
{
    extern __shared__ float smem[];
    float* sT = smem;                 // 128x128 swizzled
    float* sW = smem + 128 * 128;     // 128x128
    float* sRed = smem + 2 * 128 * 128;  // 128x17
    float* sB = sRed + 128 * 17;      // 128
    float* sW2 = sB + 128;            // 128

    const int tid = threadIdx.x;
    const int e0 = blockIdx.x * 128;
    const float4* hs4 = (const float4*)g_hs;
    const float4* hd4 = (const float4*)g_hd;
    float4* sT4 = (float4*)sT;
    const float4* W4 = (const float4*)Wa1;
    float4* sW4 = (float4*)sW;

#pragma unroll
    for (int it = 0; it < 16; ++it) {
        int idx = it * 256 + tid;
        int r = idx >> 5, c4 = idx & 31;
        int e = e0 + r;
        int si = src_idx[e], di = dst_idx[e];
        float4 u = hs4[si * 32 + c4];
        float4 v = hd4[di * 32 + c4];
        float4 t;
        t.x = lrelu(u.x + v.x); t.y = lrelu(u.y + v.y);
        t.z = lrelu(u.z + v.z); t.w = lrelu(u.w + v.w);
        sT4[r * 32 + (c4 ^ ((r >> 2) & 7))] = t;
        sW4[idx] = W4[idx];
    }
    if (tid < 128) { sB[tid] = ba1[tid]; sW2[tid] = Wa2[tid]; }
    __syncthreads();

    const int tx = tid & 15, ty = tid >> 4;
    unsigned long long acc[8][4];
#pragma unroll
    for (int i = 0; i < 8; ++i)
#pragma unroll
        for (int j = 0; j < 4; ++j) acc[i][j] = 0ull;

    const ulonglong2* sw128 = (const ulonglong2*)sW;
    const int swz = (ty & 7) << 2;
    const int rb0 = (ty * 4) * 128;
    const int rb1 = (64 + ty * 4) * 128;

#pragma unroll 4
    for (int k = 0; k < 128; ++k) {
        int ks = k ^ swz;
        float a[8];
#pragma unroll
        for (int i = 0; i < 4; ++i) {
            a[i]     = sT[rb0 + i * 128 + ks];
            a[4 + i] = sT[rb1 + i * 128 + ks];
        }
        ulonglong2 q0 = sw128[k * 32 + tx];
        ulonglong2 q1 = sw128[k * 32 + 16 + tx];
        unsigned long long wp[4] = {q0.x, q0.y, q1.x, q1.y};
        unsigned long long ap[8];
#pragma unroll
        for (int i = 0; i < 8; ++i)
            asm("mov.b64 %0, {%1, %1};" : "=l"(ap[i]) : "f"(a[i]));
#pragma unroll
        for (int i = 0; i < 8; ++i)
#pragma unroll
            for (int j = 0; j < 4; ++j)
                asm("fma.rn.f32x2 %0, %1, %2, %0;"
                    : "+l"(acc[i][j]) : "l"(ap[i]), "l"(wp[j]));
    }

    const float4* sB4 = (const float4*)sB;
    const float4* sW24 = (const float4*)sW2;
    float4 bb0 = sB4[tx], bb1 = sB4[16 + tx];
    float4 ww0 = sW24[tx], ww1 = sW24[16 + tx];
    float bcol[8] = {bb0.x, bb0.y, bb0.z, bb0.w, bb1.x, bb1.y, bb1.z, bb1.w};
    float wcol[8] = {ww0.x, ww0.y, ww0.z, ww0.w, ww1.x, ww1.y, ww1.z, ww1.w};

#pragma unroll
    for (int i = 0; i < 8; ++i) {
        int r = (i < 4) ? (ty * 4 + i) : (64 + ty * 4 + i - 4);
        float o[8];
#pragma unroll
        for (int j = 0; j < 4; ++j)
            asm("mov.b64 {%0, %1}, %2;" : "=f"(o[2 * j]), "=f"(o[2 * j + 1]) : "l"(acc[i][j]));
        float pr = 0.f;
#pragma unroll
        for (int j = 0; j < 8; ++j)
            pr += lrelu(o[j] + bcol[j]) * wcol[j];
        sRed[r * 17 + tx] = pr;
    }
    __syncthreads();
    if (tid < 128) {
        float s = ba2[0];
#pragma unroll
        for (int t = 0; t < 16; ++t) s += sRed[tid * 17 + t];
        g_score[e0 + tid] = s;
    }
}

// ---------------- CSR build: count / scan / scatter ----------------
__global__ void k_zero()
{
    int i = blockIdx.x * 256 + threadIdx.x;
    if (i < NDST) { g_count[i] = 0; g_cursor[i] = 0; }
}

__global__ void k_hist(const int* __restrict__ dst_idx)
{
    int e = blockIdx.x * 256 + threadIdx.x;
    if (e < NEDGE) atomicAdd(&g_count[dst_idx[e]], 1);
}

__global__ void k_scan1()
{
    int tid = threadIdx.x;
    int gid = blockIdx.x * 1024 + tid;
    int v = (gid < NDST) ? g_count[gid] : 0;
    int lane = tid & 31, w = tid >> 5;
    int x = v;
#pragma unroll
    for (int o = 1; o < 32; o <<= 1) {
        int y = __shfl_up_sync(0xffffffffu, x, o);
        if (lane >= o) x += y;
    }
    __shared__ int ws[32];
    if (lane == 31) ws[w] = x;
    __syncthreads();
    if (w == 0) {
        int y = ws[lane];
#pragma unroll
        for (int o = 1; o < 32; o <<= 1) {
            int z = __shfl_up_sync(0xffffffffu, y, o);
            if (lane >= o) y += z;
        }
        ws[lane] = y;
    }
    __syncthreads();
    int pref = (w > 0) ? ws[w - 1] : 0;
    int incl = x + pref;
    if (gid < NDST) g_offset[gid] = incl - v;  // exclusive
    if (tid == 1023) g_bsums[blockIdx.x] = incl;
}

__global__ void k_scan2(int nblocks)
{
    int tid = threadIdx.x;  // 64
    int v = (tid < nblocks) ? g_bsums[tid] : 0;
    int lane = tid & 31, w = tid >> 5;
    int x = v;
#pragma unroll
    for (int o = 1; o < 32; o <<= 1) {
        int y = __shfl_up_sync(0xffffffffu, x, o);
        if (lane >= o) x += y;
    }
    __shared__ int ws[2];
    if (lane == 31) ws[w] = x;
    __syncthreads();
    if (w == 1) x += ws[0];
    g_bsums2[tid] = x - v;  // exclusive
}

__global__ void k_scan3()
{
    int gid = blockIdx.x * 1024 + threadIdx.x;
    if (gid < NDST) g_offset[gid] += g_bsums2[blockIdx.x];
    if (gid == 0) g_offset[NDST] = NEDGE;
}

__global__ void k_scatter(const int* __restrict__ dst_idx)
{
    int e = blockIdx.x * 256 + threadIdx.x;
    if (e < NEDGE) {
        int d = dst_idx[e];
        int p = atomicAdd(&g_cursor[d], 1);
        g_eorder[g_offset[d] + p] = e;
    }
}

// ---------------- softmax + aggregate: one warp per dst node ----------------
// n_f[d] = sum_e alpha_e * hs[src_e] + hd[d]   (since sum alpha = 1)
__global__ void k_aggregate(const int* __restrict__ src_idx)
{
    int gw = (blockIdx.x * blockDim.x + threadIdx.x) >> 5;
    int lane = threadIdx.x & 31;
    if (gw >= NDST) return;
    int beg = g_offset[gw], end = g_offset[gw + 1];

    const float4* hs4 = (const float4*)g_hs;
    const float4* hd4 = (const float4*)g_hd;
    float4 acc = make_float4(0.f, 0.f, 0.f, 0.f);

    if (end > beg) {
        float m = __int_as_float(0xff800000);  // -inf
        for (int i = beg + lane; i < end; i += 32)
            m = fmaxf(m, g_score[g_eorder[i]]);
#pragma unroll
        for (int o = 16; o; o >>= 1) m = fmaxf(m, __shfl_xor_sync(0xffffffffu, m, o));

        float dsum = 0.f;
        for (int i = beg + lane; i < end; i += 32)
            dsum += __expf(g_score[g_eorder[i]] - m);
#pragma unroll
        for (int o = 16; o; o >>= 1) dsum += __shfl_xor_sync(0xffffffffu, dsum, o);
        float inv = 1.f / dsum;

        for (int i = beg; i < end; ++i) {
            int e = g_eorder[i];
            float w = __expf(g_score[e] - m) * inv;
            int s = src_idx[e];
            float4 h = hs4[s * 32 + lane];
            acc.x += w * h.x; acc.y += w * h.y; acc.z += w * h.z; acc.w += w * h.w;
        }
        float4 hv = hd4[gw * 32 + lane];
        acc.x += hv.x; acc.y += hv.y; acc.z += hv.z; acc.w += hv.w;
    }
    ((float4*)g_nf)[gw * 32 + lane] = acc;
}

// ---------------- launch ----------------
extern "C" void kernel_launch(void* const* d_in, const int* in_sizes, int n_in,
                              void* d_out, int out_size)
{
    const float* feat_src = (const float*)d_in[0];
    const float* feat_dst = (const float*)d_in[1];
    const int*   src_idx  = (const int*)d_in[2];
    const int*   dst_idx  = (const int*)d_in[3];
    const float* W_src = (const float*)d_in[4];
    const float* b_src = (const float*)d_in[5];
    const float* W_dst = (const float*)d_in[6];
    const float* b_dst = (const float*)d_in[7];
    const float* W_a1  = (const float*)d_in[8];
    const float* b_a1  = (const float*)d_in[9];
    const float* W_a2  = (const float*)d_in[10];
    const float* b_a2  = (const float*)d_in[11];
    const float* W_out = (const float*)d_in[12];
    const float* b_out = (const float*)d_in[13];
    float* out = (float*)d_out;

    float *hs_p, *hd_p, *nf_p;
    cudaGetSymbolAddress((void**)&hs_p, g_hs);
    cudaGetSymbolAddress((void**)&hd_p, g_hd);
    cudaGetSymbolAddress((void**)&nf_p, g_nf);

    const int smem_gemm = 2 * 128 * 128 * 4;                          // 131072
    const int smem_edge = 2 * 128 * 128 * 4 + 128 * 17 * 4 + 2 * 128 * 4;  // 140800
    cudaFuncSetAttribute(gemm_node, cudaFuncAttributeMaxDynamicSharedMemorySize, smem_gemm);
    cudaFuncSetAttribute(edge_score, cudaFuncAttributeMaxDynamicSharedMemorySize, smem_edge);

    const int gemm_blocks = (NSRC + 127) / 128;  // 391
    const int edge_blocks = NEDGE / 128;         // 5000
    const int scan_blocks = (NDST + 1023) / 1024;  // 49

    // 1. node projections
    gemm_node<<<gemm_blocks, 256, smem_gemm>>>(feat_src, W_src, b_src, hs_p, NSRC, 0);
    gemm_node<<<gemm_blocks, 256, smem_gemm>>>(feat_dst, W_dst, b_dst, hd_p, NDST, 0);

    // 2. per-edge attention scores
    edge_score<<<edge_blocks, 256, smem_edge>>>(src_idx, dst_idx, W_a1, b_a1, W_a2, b_a2);

    // 3. CSR build (edges grouped by dst)
    k_zero<<<(NDST + 255) / 256, 256>>>();
    k_hist<<<(NEDGE + 255) / 256, 256>>>(dst_idx);
    k_scan1<<<scan_blocks, 1024>>>();
    k_scan2<<<1, 64>>>(scan_blocks);
    k_scan3<<<scan_blocks, 1024>>>();
    k_scatter<<<(NEDGE + 255) / 256, 256>>>(dst_idx);

    // 4. segment softmax + weighted aggregation
    k_aggregate<<<(NDST * 32 + 255) / 256, 256>>>(src_idx);

    // 5. output projection + leaky relu -> d_out
    gemm_node<<<gemm_blocks, 256, smem_gemm>>>(nf_p, W_out, b_out, out, NDST, 1);
}

// round 9
// speedup vs baseline: 1.4968x; 1.4968x over previous
#include <cuda_runtime.h>
#include <cuda_bf16.h>
#include <cstdint>

#define D 128
#define NSRC 50000
#define NDST 50000
#define NEDGE 640000
#define NTILES (NEDGE / 128)
#define NEG_SLOPE 0.01f

// ---------------- device scratch (static, no allocation) ----------------
__device__ float g_hs[NSRC * D];
__device__ float g_hd[NDST * D];
__device__ float g_nf[NDST * D];
__device__ float g_score[NEDGE];
__device__ int g_count[NDST];
__device__ int g_offset[NDST + 1];
__device__ int g_cursor[NDST];
__device__ int g_eorder[NEDGE];
__device__ int g_bsums[64];
__device__ int g_bsums2[64];

__device__ __forceinline__ float lrelu(float x) { return x > 0.f ? x : NEG_SLOPE * x; }

// Swizzled element offset inside a [128 rows x 128 cols] bf16 tile:
// 8-col groups XORed with (row & 7)  ->  conflict-free ldmatrix & stores.
__device__ __forceinline__ uint32_t swz_off(int r, int c) {
    return (uint32_t)((r << 7) + ((((c >> 3) ^ (r & 7)) << 3) + (c & 7)));
}

__device__ __forceinline__ uint32_t smem_u32(const void* p) {
    uint32_t a;
    asm("{ .reg .u64 t; cvta.to.shared.u64 t, %1; cvt.u32.u64 %0, t; }" : "=r"(a) : "l"(p));
    return a;
}

#define LDSM_X4(r0, r1, r2, r3, addr) \
    asm volatile("ldmatrix.sync.aligned.m8n8.x4.shared.b16 {%0,%1,%2,%3}, [%4];" \
        : "=r"(r0), "=r"(r1), "=r"(r2), "=r"(r3) : "r"(addr))
#define LDSM_X4_T(r0, r1, r2, r3, addr) \
    asm volatile("ldmatrix.sync.aligned.m8n8.x4.trans.shared.b16 {%0,%1,%2,%3}, [%4];" \
        : "=r"(r0), "=r"(r1), "=r"(r2), "=r"(r3) : "r"(addr))
#define MMA_BF16(c0, c1, c2, c3, a0, a1, a2, a3, b0, b1) \
    asm volatile("mma.sync.aligned.m16n8k16.row.col.f32.bf16.bf16.f32 " \
        "{%0,%1,%2,%3}, {%4,%5,%6,%7}, {%8,%9}, {%0,%1,%2,%3};" \
        : "+f"(c0), "+f"(c1), "+f"(c2), "+f"(c3) \
        : "r"(a0), "r"(a1), "r"(a2), "r"(a3), "r"(b0), "r"(b1))

// =======================================================================
// Node GEMM (fp32 f32x2 FMA core) — unchanged, proven.
// =======================================================================
__global__ __launch_bounds__(256, 1)
void gemm_node(const float* __restrict__ A, const float* __restrict__ W,
               const float* __restrict__ bias, float* __restrict__ Out,
               int nrows, int act)
{
    extern __shared__ float smem[];
    float* sA = smem;
    float* sW = smem + 128 * 128;

    const int tid = threadIdx.x;
    const int row0 = blockIdx.x * 128;
    const float4* A4 = (const float4*)A;
    const float4* W4 = (const float4*)W;
    float4* sA4 = (float4*)sA;
    float4* sW4 = (float4*)sW;

#pragma unroll
    for (int it = 0; it < 16; ++it) {
        int idx = it * 256 + tid;
        int r = idx >> 5, c4 = idx & 31;
        int gr = row0 + r;
        float4 v = make_float4(0.f, 0.f, 0.f, 0.f);
        if (gr < nrows) v = A4[gr * 32 + c4];
        sA4[r * 32 + (c4 ^ ((r >> 2) & 7))] = v;
        sW4[idx] = W4[idx];
    }
    __syncthreads();

    const int tx = tid & 15, ty = tid >> 4;
    unsigned long long acc[8][4];
#pragma unroll
    for (int i = 0; i < 8; ++i)
#pragma unroll
        for (int j = 0; j < 4; ++j) acc[i][j] = 0ull;

    const ulonglong2* sw128 = (const ulonglong2*)sW;
    const int swz = (ty & 7) << 2;
    const int rb0 = (ty * 4) * 128;
    const int rb1 = (64 + ty * 4) * 128;

#pragma unroll 4
    for (int k = 0; k < 128; ++k) {
        int ks = k ^ swz;
        float a[8];
#pragma unroll
        for (int i = 0; i < 4; ++i) {
            a[i]     = sA[rb0 + i * 128 + ks];
            a[4 + i] = sA[rb1 + i * 128 + ks];
        }
        ulonglong2 q0 = sw128[k * 32 + tx];
        ulonglong2 q1 = sw128[k * 32 + 16 + tx];
        unsigned long long wp[4] = {q0.x, q0.y, q1.x, q1.y};
        unsigned long long ap[8];
#pragma unroll
        for (int i = 0; i < 8; ++i)
            asm("mov.b64 %0, {%1, %1};" : "=l"(ap[i]) : "f"(a[i]));
#pragma unroll
        for (int i = 0; i < 8; ++i)
#pragma unroll
            for (int j = 0; j < 4; ++j)
                asm("fma.rn.f32x2 %0, %1, %2, %0;"
                    : "+l"(acc[i][j]) : "l"(ap[i]), "l"(wp[j]));
    }

    const float4* b4 = (const float4*)bias;
    float4 bb0 = b4[tx], bb1 = b4[16 + tx];
    float bcol[8] = {bb0.x, bb0.y, bb0.z, bb0.w, bb1.x, bb1.y, bb1.z, bb1.w};
    float4* Out4 = (float4*)Out;
#pragma unroll
    for (int i = 0; i < 8; ++i) {
        int r = (i < 4) ? (ty * 4 + i) : (64 + ty * 4 + i - 4);
        int gr = row0 + r;
        if (gr >= nrows) continue;
        float o[8];
#pragma unroll
        for (int j = 0; j < 4; ++j)
            asm("mov.b64 {%0, %1}, %2;" : "=f"(o[2 * j]), "=f"(o[2 * j + 1]) : "l"(acc[i][j]));
#pragma unroll
        for (int j = 0; j < 8; ++j) {
            o[j] += bcol[j];
            if (act) o[j] = lrelu(o[j]);
        }
        Out4[gr * 32 + tx]      = make_float4(o[0], o[1], o[2], o[3]);
        Out4[gr * 32 + 16 + tx] = make_float4(o[4], o[5], o[6], o[7]);
    }
}

// =======================================================================
// Edge scoring via warp-level HMMA (mma.sync bf16, 3-term split).
// Persistent: grid = #SMs. Split-W [k][n] staged in smem once; per
// 128-edge tile: gather+lrelu+split -> swizzled A smem -> 8 warps each
// compute 16 rows x 128 cols -> register epilogue -> g_score.
// SMEM (bf16 elems unless noted):
//   sB_hi [0,32KB)  sB_lo [32KB,64KB)  sA_hi [64KB,96KB)  sA_lo [96KB,128KB)
//   sb1 (128 f32) @128KB   sw2 (128 f32) @128K+512
// =======================================================================
#define ES_SMEM_BYTES (128 * 1024 + 1024)

__global__ __launch_bounds__(256, 1)
void edge_score_mma(const int* __restrict__ src_idx, const int* __restrict__ dst_idx,
                    const float* __restrict__ Wa1, const float* __restrict__ ba1,
                    const float* __restrict__ Wa2, const float* __restrict__ ba2)
{
    extern __shared__ float smem[];
    __nv_bfloat16* sB_hi = (__nv_bfloat16*)smem;
    __nv_bfloat16* sB_lo = sB_hi + 128 * 128;
    __nv_bfloat16* sA_hi = sB_lo + 128 * 128;
    __nv_bfloat16* sA_lo = sA_hi + 128 * 128;
    float* sb1 = (float*)(sA_lo + 128 * 128);
    float* sw2 = sb1 + 128;

    const int tid = threadIdx.x;
    const int wid = tid >> 5;
    const int lane = tid & 31;

    // ---- one-time init: split W_a1 into smem, stage b1/w2 ----
    for (int i = tid; i < D * D; i += 256) {
        int k = i >> 7, n = i & 127;
        float v = Wa1[i];
        __nv_bfloat16 hi = __float2bfloat16(v);
        float lo = v - __bfloat162float(hi);
        uint32_t off = swz_off(k, n);
        sB_hi[off] = hi;
        sB_lo[off] = __float2bfloat16(lo);
    }
    if (tid < 128) { sb1[tid] = ba1[tid]; sw2[tid] = Wa2[tid]; }
    __syncthreads();

    const float bias2 = ba2[0];
    const int g = lane >> 2;          // row group 0..7
    const int tig = lane & 3;         // quad lane

    // constant epilogue coefficients in registers
    float rb[16][2], rw[16][2];
#pragma unroll
    for (int nt = 0; nt < 16; ++nt) {
        int n = nt * 8 + tig * 2;
        rb[nt][0] = sb1[n];     rb[nt][1] = sb1[n + 1];
        rw[nt][0] = sw2[n];     rw[nt][1] = sw2[n + 1];
    }

    // per-lane ldmatrix address components
    // A frag (no trans): r = wid*16 + (lane&7) + ((lane>>3)&1)*8 ; c = ks*16 + ((lane>>4)&1)*8
    const int a_r = wid * 16 + (lane & 7) + ((lane >> 3) & 1) * 8;
    const int a_cgrp = (lane >> 4) & 1;                 // adds 1 to (c>>3)
    const uint32_t aband = (uint32_t)(a_r << 7) * 2u;   // byte offset of row
    const int a_r7 = a_r & 7;
    const uint32_t sAhi_base = smem_u32(sA_hi);
    const uint32_t sAlo_base = smem_u32(sA_lo);
    // B frag (trans): k = ks*16 + (lane&7) + ((lane>>3)&1)*8 ; n = p*16 + ((lane>>4)&1)*8
    const int b_klow = (lane & 7) + ((lane >> 3) & 1) * 8;
    const int b_ngrp = (lane >> 4) & 1;
    const uint32_t sBhi_base = smem_u32(sB_hi);
    const uint32_t sBlo_base = smem_u32(sB_lo);

    const float4* hs4 = (const float4*)g_hs;
    const float4* hd4 = (const float4*)g_hd;

    const int bid = blockIdx.x;
    const int grid = gridDim.x;

    for (int tile = bid; tile < NTILES; tile += grid) {
        const int e0 = tile * 128;

        // ---- stage 1: gather + lrelu + bf16 hi/lo split into smem A ----
#pragma unroll 4
        for (int it = 0; it < 16; ++it) {
            int idx = it * 256 + tid;
            int r = idx >> 5, c4 = idx & 31;
            int e = e0 + r;
            int si = __ldg(&src_idx[e]);
            int di = __ldg(&dst_idx[e]);
            float4 u = hs4[si * 32 + c4];
            float4 v = hd4[di * 32 + c4];
            float t0 = lrelu(u.x + v.x), t1 = lrelu(u.y + v.y);
            float t2 = lrelu(u.z + v.z), t3 = lrelu(u.w + v.w);
            uint32_t hi01, hi23;
            asm("cvt.rn.bf16x2.f32 %0, %1, %2;" : "=r"(hi01) : "f"(t1), "f"(t0));
            asm("cvt.rn.bf16x2.f32 %0, %1, %2;" : "=r"(hi23) : "f"(t3), "f"(t2));
            float h0 = __uint_as_float(hi01 << 16);
            float h1 = __uint_as_float(hi01 & 0xffff0000u);
            float h2 = __uint_as_float(hi23 << 16);
            float h3 = __uint_as_float(hi23 & 0xffff0000u);
            uint32_t lo01, lo23;
            asm("cvt.rn.bf16x2.f32 %0, %1, %2;" : "=r"(lo01) : "f"(t1 - h1), "f"(t0 - h0));
            asm("cvt.rn.bf16x2.f32 %0, %1, %2;" : "=r"(lo23) : "f"(t3 - h3), "f"(t2 - h2));
            uint32_t off = swz_off(r, c4 * 4);      // 4 cols within one 8-group
            *(uint2*)((char*)sA_hi + off * 2) = make_uint2(hi01, hi23);
            *(uint2*)((char*)sA_lo + off * 2) = make_uint2(lo01, lo23);
        }
        __syncthreads();

        // ---- stage 2: HMMA — warp wid computes rows wid*16..+15, all 128 cols ----
        float acc[16][4];
#pragma unroll
        for (int nt = 0; nt < 16; ++nt)
#pragma unroll
            for (int j = 0; j < 4; ++j) acc[nt][j] = 0.f;

#pragma unroll
        for (int ks = 0; ks < 8; ++ks) {
            // A fragments
            uint32_t a_off = aband + (uint32_t)((((2 * ks + a_cgrp) ^ a_r7) << 3) * 2);
            uint32_t ah0, ah1, ah2, ah3, al0, al1, al2, al3;
            LDSM_X4(ah0, ah1, ah2, ah3, sAhi_base + a_off);
            LDSM_X4(al0, al1, al2, al3, sAlo_base + a_off);

            const int bk = ks * 16 + b_klow;
            const uint32_t b_band = (uint32_t)(bk << 7) * 2u;
            const int bk7 = bk & 7;
#pragma unroll
            for (int p = 0; p < 8; ++p) {
                uint32_t b_off = b_band + (uint32_t)((((2 * p + b_ngrp) ^ bk7) << 3) * 2);
                uint32_t bh0, bh1, bh2, bh3, bl0, bl1, bl2, bl3;
                LDSM_X4_T(bh0, bh1, bh2, bh3, sBhi_base + b_off);
                LDSM_X4_T(bl0, bl1, bl2, bl3, sBlo_base + b_off);
                float* c0 = acc[2 * p];
                float* c1 = acc[2 * p + 1];
                MMA_BF16(c0[0], c0[1], c0[2], c0[3], ah0, ah1, ah2, ah3, bh0, bh1);
                MMA_BF16(c0[0], c0[1], c0[2], c0[3], al0, al1, al2, al3, bh0, bh1);
                MMA_BF16(c0[0], c0[1], c0[2], c0[3], ah0, ah1, ah2, ah3, bl0, bl1);
                MMA_BF16(c1[0], c1[1], c1[2], c1[3], ah0, ah1, ah2, ah3, bh2, bh3);
                MMA_BF16(c1[0], c1[1], c1[2], c1[3], al0, al1, al2, al3, bh2, bh3);
                MMA_BF16(c1[0], c1[1], c1[2], c1[3], ah0, ah1, ah2, ah3, bl2, bl3);
            }
        }

        // ---- stage 3: epilogue s = lrelu(acc + b1) . w2 (register-only) ----
        float p0 = 0.f, p1 = 0.f;
#pragma unroll
        for (int nt = 0; nt < 16; ++nt) {
            p0 += lrelu(acc[nt][0] + rb[nt][0]) * rw[nt][0]
                + lrelu(acc[nt][1] + rb[nt][1]) * rw[nt][1];
            p1 += lrelu(acc[nt][2] + rb[nt][0]) * rw[nt][0]
                + lrelu(acc[nt][3] + rb[nt][1]) * rw[nt][1];
        }
        p0 += __shfl_xor_sync(0xffffffffu, p0, 1);
        p0 += __shfl_xor_sync(0xffffffffu, p0, 2);
        p1 += __shfl_xor_sync(0xffffffffu, p1, 1);
        p1 += __shfl_xor_sync(0xffffffffu, p1, 2);
        if (tig == 0) {
            g_score[e0 + wid * 16 + g]     = p0 + bias2;
            g_score[e0 + wid * 16 + g + 8] = p1 + bias2;
        }
        __syncthreads();   // protect sA before next tile's gather
    }
}

// ---------------- CSR build: count / scan / scatter ----------------
__global__ void k_zero()
{
    int i = blockIdx.x * 256 + threadIdx.x;
    if (i < NDST) { g_count[i] = 0; g_cursor[i] = 0; }
}

__global__ void k_hist(const int* __restrict__ dst_idx)
{
    int e = blockIdx.x * 256 + threadIdx.x;
    if (e < NEDGE) atomicAdd(&g_count[dst_idx[e]], 1);
}

__global__ void k_scan1()
{
    int tid = threadIdx.x;
    int gid = blockIdx.x * 1024 + tid;
    int v = (gid < NDST) ? g_count[gid] : 0;
    int lane = tid & 31, w = tid >> 5;
    int x = v;
#pragma unroll
    for (int o = 1; o < 32; o <<= 1) {
        int y = __shfl_up_sync(0xffffffffu, x, o);
        if (lane >= o) x += y;
    }
    __shared__ int ws[32];
    if (lane == 31) ws[w] = x;
    __syncthreads();
    if (w == 0) {
        int y = ws[lane];
#pragma unroll
        for (int o = 1; o < 32; o <<= 1) {
            int z = __shfl_up_sync(0xffffffffu, y, o);
            if (lane >= o) y += z;
        }
        ws[lane] = y;
    }
    __syncthreads();
    int pref = (w > 0) ? ws[w - 1] : 0;
    int incl = x + pref;
    if (gid < NDST) g_offset[gid] = incl - v;
    if (tid == 1023) g_bsums[blockIdx.x] = incl;
}

__global__ void k_scan2(int nblocks)
{
    int tid = threadIdx.x;
    int v = (tid < nblocks) ? g_bsums[tid] : 0;
    int lane = tid & 31, w = tid >> 5;
    int x = v;
#pragma unroll
    for (int o = 1; o < 32; o <<= 1) {
        int y = __shfl_up_sync(0xffffffffu, x, o);
        if (lane >= o) x += y;
    }
    __shared__ int ws[2];
    if (lane == 31) ws[w] = x;
    __syncthreads();
    if (w == 1) x += ws[0];
    g_bsums2[tid] = x - v;
}

__global__ void k_scan3()
{
    int gid = blockIdx.x * 1024 + threadIdx.x;
    if (gid < NDST) g_offset[gid] += g_bsums2[blockIdx.x];
    if (gid == 0) g_offset[NDST] = NEDGE;
}

__global__ void k_scatter(const int* __restrict__ dst_idx)
{
    int e = blockIdx.x * 256 + threadIdx.x;
    if (e < NEDGE) {
        int d = dst_idx[e];
        int p = atomicAdd(&g_cursor[d], 1);
        g_eorder[g_offset[d] + p] = e;
    }
}

// ---------------- softmax + aggregate: one warp per dst node ----------------
__global__ void k_aggregate(const int* __restrict__ src_idx)
{
    int gw = (blockIdx.x * blockDim.x + threadIdx.x) >> 5;
    int lane = threadIdx.x & 31;
    if (gw >= NDST) return;
    int beg = g_offset[gw], end = g_offset[gw + 1];

    const float4* hs4 = (const float4*)g_hs;
    const float4* hd4 = (const float4*)g_hd;
    float4 acc = make_float4(0.f, 0.f, 0.f, 0.f);

    if (end > beg) {
        float m = __int_as_float(0xff800000);
        for (int i = beg + lane; i < end; i += 32)
            m = fmaxf(m, g_score[g_eorder[i]]);
#pragma unroll
        for (int o = 16; o; o >>= 1) m = fmaxf(m, __shfl_xor_sync(0xffffffffu, m, o));

        float dsum = 0.f;
        for (int i = beg + lane; i < end; i += 32)
            dsum += __expf(g_score[g_eorder[i]] - m);
#pragma unroll
        for (int o = 16; o; o >>= 1) dsum += __shfl_xor_sync(0xffffffffu, dsum, o);
        float inv = 1.f / dsum;

        for (int i = beg; i < end; ++i) {
            int e = g_eorder[i];
            float w = __expf(g_score[e] - m) * inv;
            int s = src_idx[e];
            float4 h = hs4[s * 32 + lane];
            acc.x += w * h.x; acc.y += w * h.y; acc.z += w * h.z; acc.w += w * h.w;
        }
        float4 hv = hd4[gw * 32 + lane];
        acc.x += hv.x; acc.y += hv.y; acc.z += hv.z; acc.w += hv.w;
    }
    ((float4*)g_nf)[gw * 32 + lane] = acc;
}

// ---------------- launch ----------------
extern "C" void kernel_launch(void* const* d_in, const int* in_sizes, int n_in,
                              void* d_out, int out_size)
{
    const float* feat_src = (const float*)d_in[0];
    const float* feat_dst = (const float*)d_in[1];
    const int*   src_idx  = (const int*)d_in[2];
    const int*   dst_idx  = (const int*)d_in[3];
    const float* W_src = (const float*)d_in[4];
    const float* b_src = (const float*)d_in[5];
    const float* W_dst = (const float*)d_in[6];
    const float* b_dst = (const float*)d_in[7];
    const float* W_a1  = (const float*)d_in[8];
    const float* b_a1  = (const float*)d_in[9];
    const float* W_a2  = (const float*)d_in[10];
    const float* b_a2  = (const float*)d_in[11];
    const float* W_out = (const float*)d_in[12];
    const float* b_out = (const float*)d_in[13];
    float* out = (float*)d_out;

    float *hs_p, *hd_p, *nf_p;
    cudaGetSymbolAddress((void**)&hs_p, g_hs);
    cudaGetSymbolAddress((void**)&hd_p, g_hd);
    cudaGetSymbolAddress((void**)&nf_p, g_nf);

    int nsm = 148;
    cudaDeviceGetAttribute(&nsm, cudaDevAttrMultiProcessorCount, 0);
    if (nsm <= 0 || nsm > NTILES) nsm = 148;

    const int smem_gemm = 2 * 128 * 128 * 4;
    cudaFuncSetAttribute(gemm_node, cudaFuncAttributeMaxDynamicSharedMemorySize, smem_gemm);
    cudaFuncSetAttribute(edge_score_mma, cudaFuncAttributeMaxDynamicSharedMemorySize, ES_SMEM_BYTES);

    const int gemm_blocks = (NSRC + 127) / 128;
    const int scan_blocks = (NDST + 1023) / 1024;

    // 1. node projections (fp32)
    gemm_node<<<gemm_blocks, 256, smem_gemm>>>(feat_src, W_src, b_src, hs_p, NSRC, 0);
    gemm_node<<<gemm_blocks, 256, smem_gemm>>>(feat_dst, W_dst, b_dst, hd_p, NDST, 0);

    // 2. CSR build (edges grouped by dst)
    k_zero<<<(NDST + 255) / 256, 256>>>();
    k_hist<<<(NEDGE + 255) / 256, 256>>>(dst_idx);
    k_scan1<<<scan_blocks, 1024>>>();
    k_scan2<<<1, 64>>>(scan_blocks);
    k_scan3<<<scan_blocks, 1024>>>();
    k_scatter<<<(NEDGE + 255) / 256, 256>>>(dst_idx);

    // 3. per-edge attention scores via HMMA (persistent)
    edge_score_mma<<<nsm, 256, ES_SMEM_BYTES>>>(src_idx, dst_idx, W_a1, b_a1, W_a2, b_a2);

    // 4. segment softmax + weighted aggregation
    k_aggregate<<<(NDST * 32 + 255) / 256, 256>>>(src_idx);

    // 5. output projection + leaky relu -> d_out
    gemm_node<<<gemm_blocks, 256, smem_gemm>>>(nf_p, W_out, b_out, out, NDST, 1);
}

// round 10
// speedup vs baseline: 1.7065x; 1.1401x over previous
#include <cuda_runtime.h>
#include <cuda_bf16.h>
#include <cstdint>

#define D 128
#define NSRC 50000
#define NDST 50000
#define NEDGE 640000
#define NTILES (NEDGE / 128)
#define NEG_SLOPE 0.01f

// ---------------- device scratch (static, no allocation) ----------------
__device__ float g_hs[NSRC * D];
__device__ float g_hd[NDST * D];
__device__ float g_nf[NDST * D];
__device__ float g_score[NEDGE];
__device__ int g_count[NDST];
__device__ int g_offset[NDST + 1];
__device__ int g_cursor[NDST];
__device__ int g_eorder[NEDGE];
__device__ int g_bsums[64];
__device__ int g_bsums2[64];

__device__ __forceinline__ float lrelu(float x) { return x > 0.f ? x : NEG_SLOPE * x; }

// Swizzled element offset inside a [128 rows x 128 cols] bf16 tile.
__device__ __forceinline__ uint32_t swz_off(int r, int c) {
    return (uint32_t)((r << 7) + ((((c >> 3) ^ (r & 7)) << 3) + (c & 7)));
}

__device__ __forceinline__ uint32_t smem_u32(const void* p) {
    uint32_t a;
    asm("{ .reg .u64 t; cvta.to.shared.u64 t, %1; cvt.u32.u64 %0, t; }" : "=r"(a) : "l"(p));
    return a;
}

#define LDSM_X4(r0, r1, r2, r3, addr) \
    asm volatile("ldmatrix.sync.aligned.m8n8.x4.shared.b16 {%0,%1,%2,%3}, [%4];" \
        : "=r"(r0), "=r"(r1), "=r"(r2), "=r"(r3) : "r"(addr))
#define LDSM_X4_T(r0, r1, r2, r3, addr) \
    asm volatile("ldmatrix.sync.aligned.m8n8.x4.trans.shared.b16 {%0,%1,%2,%3}, [%4];" \
        : "=r"(r0), "=r"(r1), "=r"(r2), "=r"(r3) : "r"(addr))
#define MMA_BF16(c0, c1, c2, c3, a0, a1, a2, a3, b0, b1) \
    asm volatile("mma.sync.aligned.m16n8k16.row.col.f32.bf16.bf16.f32 " \
        "{%0,%1,%2,%3}, {%4,%5,%6,%7}, {%8,%9}, {%0,%1,%2,%3};" \
        : "+f"(c0), "+f"(c1), "+f"(c2), "+f"(c3) \
        : "r"(a0), "r"(a1), "r"(a2), "r"(a3), "r"(b0), "r"(b1))

// split one fp32 into bf16 hi/lo pair packed as bf16x2 words (2 values)
__device__ __forceinline__ void split2(float t0, float t1, uint32_t& hi, uint32_t& lo) {
    asm("cvt.rn.bf16x2.f32 %0, %1, %2;" : "=r"(hi) : "f"(t1), "f"(t0));
    float h0 = __uint_as_float(hi << 16);
    float h1 = __uint_as_float(hi & 0xffff0000u);
    asm("cvt.rn.bf16x2.f32 %0, %1, %2;" : "=r"(lo) : "f"(t1 - h1), "f"(t0 - h0));
}

// =======================================================================
// Node GEMM via HMMA (3-term bf16 split). One 128x128 tile per block.
// Warp tiling 4x2: warp = (rg, cg) computes rows rg*32..+31, cols cg*64..+63.
// SMEM: sWB hi/lo (64KB) + sAB hi/lo (64KB) + bias (512B).
// =======================================================================
#define GN_SMEM (128 * 1024 + 512)

__global__ __launch_bounds__(256, 1)
void gemm_node_tc(const float* __restrict__ A, const float* __restrict__ W,
                  const float* __restrict__ bias, float* __restrict__ Out,
                  int nrows, int act)
{
    extern __shared__ float smem[];
    char* smc = (char*)smem;
    char* sWB_hi = smc;                     // 32KB
    char* sWB_lo = smc + 32768;
    char* sAB_hi = smc + 65536;
    char* sAB_lo = smc + 98304;
    float* sbias = (float*)(smc + 131072);  // 128 f32

    const int tid = threadIdx.x;
    const int wid = tid >> 5;
    const int lane = tid & 31;
    const int row0 = blockIdx.x * 128;

    // stage W split (swizzled [k][n])
    for (int i = tid; i < D * D; i += 256) {
        int k = i >> 7, n = i & 127;
        float v = W[i];
        __nv_bfloat16 hi = __float2bfloat16(v);
        float lo = v - __bfloat162float(hi);
        uint32_t off = swz_off(k, n);
        ((__nv_bfloat16*)sWB_hi)[off] = hi;
        ((__nv_bfloat16*)sWB_lo)[off] = __float2bfloat16(lo);
    }
    // stage A split (swizzled [r][k])
    {
        const float4* A4 = (const float4*)A;
#pragma unroll 4
        for (int it = 0; it < 16; ++it) {
            int idx = it * 256 + tid;
            int r = idx >> 5, c4 = idx & 31;
            int gr = row0 + r;
            float4 v = make_float4(0.f, 0.f, 0.f, 0.f);
            if (gr < nrows) v = A4[gr * 32 + c4];
            uint32_t hi01, lo01, hi23, lo23;
            split2(v.x, v.y, hi01, lo01);
            split2(v.z, v.w, hi23, lo23);
            uint32_t off = swz_off(r, c4 * 4) * 2;
            *(uint2*)(sAB_hi + off) = make_uint2(hi01, hi23);
            *(uint2*)(sAB_lo + off) = make_uint2(lo01, lo23);
        }
    }
    if (tid < 128) sbias[tid] = bias[tid];
    __syncthreads();

    const int rg = wid & 3, cg = wid >> 2;
    const int row_lo = (lane & 7) + ((lane >> 3) & 1) * 8;
    const int acg = (lane >> 4) & 1;
    const int x7 = lane & 7;
    const int g = lane >> 2;
    const int tig = lane & 3;
    const uint32_t sA_hi_b = smem_u32(sAB_hi);
    const uint32_t sA_lo_b = smem_u32(sAB_lo);
    const uint32_t sB_hi_b = smem_u32(sWB_hi);
    const uint32_t sB_lo_b = smem_u32(sWB_lo);

    float acc[2][8][4];
#pragma unroll
    for (int rc = 0; rc < 2; ++rc)
#pragma unroll
        for (int np = 0; np < 8; ++np)
#pragma unroll
            for (int j = 0; j < 4; ++j) acc[rc][np][j] = 0.f;

#pragma unroll
    for (int ks = 0; ks < 8; ++ks) {
        uint32_t ah[2][4], al[2][4];
#pragma unroll
        for (int rc = 0; rc < 2; ++rc) {
            uint32_t a_off = (uint32_t)((rg * 32 + rc * 16 + row_lo) << 8)
                           + (uint32_t)((((2 * ks + acg) ^ x7) << 4));
            LDSM_X4(ah[rc][0], ah[rc][1], ah[rc][2], ah[rc][3], sA_hi_b + a_off);
            LDSM_X4(al[rc][0], al[rc][1], al[rc][2], al[rc][3], sA_lo_b + a_off);
        }
        const int bk = ks * 16 + row_lo;
#pragma unroll
        for (int p = 0; p < 4; ++p) {
            int cidx = 2 * (cg * 4 + p) + acg;
            uint32_t b_off = (uint32_t)(bk << 8) + (uint32_t)(((cidx ^ x7) << 4));
            uint32_t bh0, bh1, bh2, bh3, bl0, bl1, bl2, bl3;
            LDSM_X4_T(bh0, bh1, bh2, bh3, sB_hi_b + b_off);
            LDSM_X4_T(bl0, bl1, bl2, bl3, sB_lo_b + b_off);
#pragma unroll
            for (int rc = 0; rc < 2; ++rc) {
                float* c0 = acc[rc][2 * p];
                float* c1 = acc[rc][2 * p + 1];
                MMA_BF16(c0[0], c0[1], c0[2], c0[3], ah[rc][0], ah[rc][1], ah[rc][2], ah[rc][3], bh0, bh1);
                MMA_BF16(c0[0], c0[1], c0[2], c0[3], al[rc][0], al[rc][1], al[rc][2], al[rc][3], bh0, bh1);
                MMA_BF16(c0[0], c0[1], c0[2], c0[3], ah[rc][0], ah[rc][1], ah[rc][2], ah[rc][3], bl0, bl1);
                MMA_BF16(c1[0], c1[1], c1[2], c1[3], ah[rc][0], ah[rc][1], ah[rc][2], ah[rc][3], bh2, bh3);
                MMA_BF16(c1[0], c1[1], c1[2], c1[3], al[rc][0], al[rc][1], al[rc][2], al[rc][3], bh2, bh3);
                MMA_BF16(c1[0], c1[1], c1[2], c1[3], ah[rc][0], ah[rc][1], ah[rc][2], ah[rc][3], bl2, bl3);
            }
        }
    }

    // epilogue: +bias, optional lrelu, fp32 store
#pragma unroll
    for (int rc = 0; rc < 2; ++rc) {
#pragma unroll
        for (int np = 0; np < 8; ++np) {
            int n = cg * 64 + np * 8 + tig * 2;
            float b0 = sbias[n], b1 = sbias[n + 1];
            int r1 = row0 + rg * 32 + rc * 16 + g;
            float v0 = acc[rc][np][0] + b0, v1 = acc[rc][np][1] + b1;
            float v2 = acc[rc][np][2] + b0, v3 = acc[rc][np][3] + b1;
            if (act) { v0 = lrelu(v0); v1 = lrelu(v1); v2 = lrelu(v2); v3 = lrelu(v3); }
            if (r1 < nrows) *(float2*)(Out + r1 * 128 + n) = make_float2(v0, v1);
            if (r1 + 8 < nrows) *(float2*)(Out + (r1 + 8) * 128 + n) = make_float2(v2, v3);
        }
    }
}

// =======================================================================
// Edge scoring via HMMA, 4x2 warp tiling, double-buffered A with the
// gather of tile t+grid interleaved into the MMA loop of tile t.
// SMEM: sB hi/lo 64KB | sA buf0 hi/lo 64KB | sA buf1 hi/lo 64KB |
//       sb1 512B | sw2 512B | sRed 1KB   = 198656 B
// =======================================================================
#define ES_SMEM_BYTES 198656

__device__ __forceinline__ void gather_chunk(
    const int* __restrict__ src_idx, const int* __restrict__ dst_idx,
    int e0, char* a_hi, char* a_lo, int tid, int it0)
{
    const float4* hs4 = (const float4*)g_hs;
    const float4* hd4 = (const float4*)g_hd;
#pragma unroll
    for (int it = it0; it < it0 + 4; ++it) {
        int idx = it * 256 + tid;
        int r = idx >> 5, c4 = idx & 31;
        int e = e0 + r;
        int si = __ldg(&src_idx[e]);
        int di = __ldg(&dst_idx[e]);
        float4 u = hs4[si * 32 + c4];
        float4 v = hd4[di * 32 + c4];
        float t0 = lrelu(u.x + v.x), t1 = lrelu(u.y + v.y);
        float t2 = lrelu(u.z + v.z), t3 = lrelu(u.w + v.w);
        uint32_t hi01, lo01, hi23, lo23;
        split2(t0, t1, hi01, lo01);
        split2(t2, t3, hi23, lo23);
        uint32_t off = swz_off(r, c4 * 4) * 2;
        *(uint2*)(a_hi + off) = make_uint2(hi01, hi23);
        *(uint2*)(a_lo + off) = make_uint2(lo01, lo23);
    }
}

__global__ __launch_bounds__(256, 1)
void edge_score_mma(const int* __restrict__ src_idx, const int* __restrict__ dst_idx,
                    const float* __restrict__ Wa1, const float* __restrict__ ba1,
                    const float* __restrict__ Wa2, const float* __restrict__ ba2)
{
    extern __shared__ float smem[];
    char* smc = (char*)smem;
    char* sB_hi = smc;                 // 32KB
    char* sB_lo = smc + 32768;
    char* sA_base = smc + 65536;       // 2 bufs x (hi 32KB + lo 32KB)
    float* sb1 = (float*)(smc + 196608);
    float* sw2 = (float*)(smc + 197120);
    float* sRed = (float*)(smc + 197632);  // 128 x 2

    const int tid = threadIdx.x;
    const int wid = tid >> 5;
    const int lane = tid & 31;

    // one-time: split W_a1, stage b1/w2
    for (int i = tid; i < D * D; i += 256) {
        int k = i >> 7, n = i & 127;
        float v = Wa1[i];
        __nv_bfloat16 hi = __float2bfloat16(v);
        float lo = v - __bfloat162float(hi);
        uint32_t off = swz_off(k, n);
        ((__nv_bfloat16*)sB_hi)[off] = hi;
        ((__nv_bfloat16*)sB_lo)[off] = __float2bfloat16(lo);
    }
    if (tid < 128) { sb1[tid] = ba1[tid]; sw2[tid] = Wa2[tid]; }

    const float bias2 = ba2[0];
    const int rg = wid & 3, cg = wid >> 2;
    const int row_lo = (lane & 7) + ((lane >> 3) & 1) * 8;
    const int acg = (lane >> 4) & 1;
    const int x7 = lane & 7;
    const int g = lane >> 2;
    const int tig = lane & 3;
    const uint32_t sB_hi_b = smem_u32(sB_hi);
    const uint32_t sB_lo_b = smem_u32(sB_lo);
    const uint32_t sA_b = smem_u32(sA_base);

    const int bid = blockIdx.x;
    const int grid = gridDim.x;

    // prefill buffer 0 with first tile
    if (bid < NTILES) {
        gather_chunk(src_idx, dst_idx, bid * 128, sA_base, sA_base + 32768, tid, 0);
        gather_chunk(src_idx, dst_idx, bid * 128, sA_base, sA_base + 32768, tid, 4);
        gather_chunk(src_idx, dst_idx, bid * 128, sA_base, sA_base + 32768, tid, 8);
        gather_chunk(src_idx, dst_idx, bid * 128, sA_base, sA_base + 32768, tid, 12);
    }
    __syncthreads();

    int buf = 0;
    for (int tile = bid; tile < NTILES; tile += grid) {
        const int nxt = tile + grid;
        const uint32_t cur_hi = sA_b + (uint32_t)buf * 65536u;
        const uint32_t cur_lo = cur_hi + 32768u;
        char* nxt_hi = sA_base + (buf ^ 1) * 65536;
        char* nxt_lo = nxt_hi + 32768;

        float acc[2][8][4];
#pragma unroll
        for (int rc = 0; rc < 2; ++rc)
#pragma unroll
            for (int np = 0; np < 8; ++np)
#pragma unroll
                for (int j = 0; j < 4; ++j) acc[rc][np][j] = 0.f;

#pragma unroll
        for (int c = 0; c < 4; ++c) {
            // interleave: issue next tile's gather chunk (LDGs fly under MMA)
            if (nxt < NTILES)
                gather_chunk(src_idx, dst_idx, nxt * 128, nxt_hi, nxt_lo, tid, c * 4);
#pragma unroll
            for (int ksi = 0; ksi < 2; ++ksi) {
                const int ks = 2 * c + ksi;
                uint32_t ah[2][4], al[2][4];
#pragma unroll
                for (int rc = 0; rc < 2; ++rc) {
                    uint32_t a_off = (uint32_t)((rg * 32 + rc * 16 + row_lo) << 8)
                                   + (uint32_t)((((2 * ks + acg) ^ x7) << 4));
                    LDSM_X4(ah[rc][0], ah[rc][1], ah[rc][2], ah[rc][3], cur_hi + a_off);
                    LDSM_X4(al[rc][0], al[rc][1], al[rc][2], al[rc][3], cur_lo + a_off);
                }
                const int bk = ks * 16 + row_lo;
#pragma unroll
                for (int p = 0; p < 4; ++p) {
                    int cidx = 2 * (cg * 4 + p) + acg;
                    uint32_t b_off = (uint32_t)(bk << 8) + (uint32_t)(((cidx ^ x7) << 4));
                    uint32_t bh0, bh1, bh2, bh3, bl0, bl1, bl2, bl3;
                    LDSM_X4_T(bh0, bh1, bh2, bh3, sB_hi_b + b_off);
                    LDSM_X4_T(bl0, bl1, bl2, bl3, sB_lo_b + b_off);
#pragma unroll
                    for (int rc = 0; rc < 2; ++rc) {
                        float* c0 = acc[rc][2 * p];
                        float* c1 = acc[rc][2 * p + 1];
                        MMA_BF16(c0[0], c0[1], c0[2], c0[3], ah[rc][0], ah[rc][1], ah[rc][2], ah[rc][3], bh0, bh1);
                        MMA_BF16(c0[0], c0[1], c0[2], c0[3], al[rc][0], al[rc][1], al[rc][2], al[rc][3], bh0, bh1);
                        MMA_BF16(c0[0], c0[1], c0[2], c0[3], ah[rc][0], ah[rc][1], ah[rc][2], ah[rc][3], bl0, bl1);
                        MMA_BF16(c1[0], c1[1], c1[2], c1[3], ah[rc][0], ah[rc][1], ah[rc][2], ah[rc][3], bh2, bh3);
                        MMA_BF16(c1[0], c1[1], c1[2], c1[3], al[rc][0], al[rc][1], al[rc][2], al[rc][3], bh2, bh3);
                        MMA_BF16(c1[0], c1[1], c1[2], c1[3], ah[rc][0], ah[rc][1], ah[rc][2], ah[rc][3], bl2, bl3);
                    }
                }
            }
        }

        // epilogue: per-warp partial dot over its 64 cols -> sRed[row][cg]
#pragma unroll
        for (int rc = 0; rc < 2; ++rc) {
            float p0 = 0.f, p1 = 0.f;
#pragma unroll
            for (int np = 0; np < 8; ++np) {
                int n = cg * 64 + np * 8 + tig * 2;
                float b0 = sb1[n], b1 = sb1[n + 1];
                float w0 = sw2[n], w1 = sw2[n + 1];
                p0 += lrelu(acc[rc][np][0] + b0) * w0 + lrelu(acc[rc][np][1] + b1) * w1;
                p1 += lrelu(acc[rc][np][2] + b0) * w0 + lrelu(acc[rc][np][3] + b1) * w1;
            }
            p0 += __shfl_xor_sync(0xffffffffu, p0, 1);
            p0 += __shfl_xor_sync(0xffffffffu, p0, 2);
            p1 += __shfl_xor_sync(0xffffffffu, p1, 1);
            p1 += __shfl_xor_sync(0xffffffffu, p1, 2);
            if (tig == 0) {
                int row = rg * 32 + rc * 16 + g;
                sRed[row * 2 + cg] = p0;
                sRed[(row + 8) * 2 + cg] = p1;
            }
        }
        __syncthreads();   // sRed ready; next A buf fully written; cur buf reads done
        if (tid < 128)
            g_score[tile * 128 + tid] = sRed[tid * 2] + sRed[tid * 2 + 1] + bias2;
        __syncthreads();   // protect sRed from next iteration's partial writes
        buf ^= 1;
    }
}

// ---------------- CSR build: count / scan / scatter ----------------
__global__ void k_zero()
{
    int i = blockIdx.x * 256 + threadIdx.x;
    if (i < NDST) { g_count[i] = 0; g_cursor[i] = 0; }
}

__global__ void k_hist(const int* __restrict__ dst_idx)
{
    int e = blockIdx.x * 256 + threadIdx.x;
    if (e < NEDGE) atomicAdd(&g_count[dst_idx[e]], 1);
}

__global__ void k_scan1()
{
    int tid = threadIdx.x;
    int gid = blockIdx.x * 1024 + tid;
    int v = (gid < NDST) ? g_count[gid] : 0;
    int lane = tid & 31, w = tid >> 5;
    int x = v;
#pragma unroll
    for (int o = 1; o < 32; o <<= 1) {
        int y = __shfl_up_sync(0xffffffffu, x, o);
        if (lane >= o) x += y;
    }
    __shared__ int ws[32];
    if (lane == 31) ws[w] = x;
    __syncthreads();
    if (w == 0) {
        int y = ws[lane];
#pragma unroll
        for (int o = 1; o < 32; o <<= 1) {
            int z = __shfl_up_sync(0xffffffffu, y, o);
            if (lane >= o) y += z;
        }
        ws[lane] = y;
    }
    __syncthreads();
    int pref = (w > 0) ? ws[w - 1] : 0;
    int incl = x + pref;
    if (gid < NDST) g_offset[gid] = incl - v;
    if (tid == 1023) g_bsums[blockIdx.x] = incl;
}

__global__ void k_scan2(int nblocks)
{
    int tid = threadIdx.x;
    int v = (tid < nblocks) ? g_bsums[tid] : 0;
    int lane = tid & 31, w = tid >> 5;
    int x = v;
#pragma unroll
    for (int o = 1; o < 32; o <<= 1) {
        int y = __shfl_up_sync(0xffffffffu, x, o);
        if (lane >= o) x += y;
    }
    __shared__ int ws[2];
    if (lane == 31) ws[w] = x;
    __syncthreads();
    if (w == 1) x += ws[0];
    g_bsums2[tid] = x - v;
}

__global__ void k_scan3()
{
    int gid = blockIdx.x * 1024 + threadIdx.x;
    if (gid < NDST) g_offset[gid] += g_bsums2[blockIdx.x];
    if (gid == 0) g_offset[NDST] = NEDGE;
}

__global__ void k_scatter(const int* __restrict__ dst_idx)
{
    int e = blockIdx.x * 256 + threadIdx.x;
    if (e < NEDGE) {
        int d = dst_idx[e];
        int p = atomicAdd(&g_cursor[d], 1);
        g_eorder[g_offset[d] + p] = e;
    }
}

// ---------------- softmax + aggregate: one warp per dst node ----------------
__global__ void k_aggregate(const int* __restrict__ src_idx)
{
    int gw = (blockIdx.x * blockDim.x + threadIdx.x) >> 5;
    int lane = threadIdx.x & 31;
    if (gw >= NDST) return;
    int beg = g_offset[gw], end = g_offset[gw + 1];

    const float4* hs4 = (const float4*)g_hs;
    const float4* hd4 = (const float4*)g_hd;
    float4 acc = make_float4(0.f, 0.f, 0.f, 0.f);

    if (end > beg) {
        float m = __int_as_float(0xff800000);
        for (int i = beg + lane; i < end; i += 32)
            m = fmaxf(m, g_score[g_eorder[i]]);
#pragma unroll
        for (int o = 16; o; o >>= 1) m = fmaxf(m, __shfl_xor_sync(0xffffffffu, m, o));

        float dsum = 0.f;
        for (int i = beg + lane; i < end; i += 32)
            dsum += __expf(g_score[g_eorder[i]] - m);
#pragma unroll
        for (int o = 16; o; o >>= 1) dsum += __shfl_xor_sync(0xffffffffu, dsum, o);
        float inv = 1.f / dsum;

        for (int i = beg; i < end; ++i) {
            int e = g_eorder[i];
            float w = __expf(g_score[e] - m) * inv;
            int s = src_idx[e];
            float4 h = hs4[s * 32 + lane];
            acc.x += w * h.x; acc.y += w * h.y; acc.z += w * h.z; acc.w += w * h.w;
        }
        float4 hv = hd4[gw * 32 + lane];
        acc.x += hv.x; acc.y += hv.y; acc.z += hv.z; acc.w += hv.w;
    }
    ((float4*)g_nf)[gw * 32 + lane] = acc;
}

// ---------------- launch ----------------
extern "C" void kernel_launch(void* const* d_in, const int* in_sizes, int n_in,
                              void* d_out, int out_size)
{
    const float* feat_src = (const float*)d_in[0];
    const float* feat_dst = (const float*)d_in[1];
    const int*   src_idx  = (const int*)d_in[2];
    const int*   dst_idx  = (const int*)d_in[3];
    const float* W_src = (const float*)d_in[4];
    const float* b_src = (const float*)d_in[5];
    const float* W_dst = (const float*)d_in[6];
    const float* b_dst = (const float*)d_in[7];
    const float* W_a1  = (const float*)d_in[8];
    const float* b_a1  = (const float*)d_in[9];
    const float* W_a2  = (const float*)d_in[10];
    const float* b_a2  = (const float*)d_in[11];
    const float* W_out = (const float*)d_in[12];
    const float* b_out = (const float*)d_in[13];
    float* out = (float*)d_out;

    float *hs_p, *hd_p, *nf_p;
    cudaGetSymbolAddress((void**)&hs_p, g_hs);
    cudaGetSymbolAddress((void**)&hd_p, g_hd);
    cudaGetSymbolAddress((void**)&nf_p, g_nf);

    int nsm = 148;
    cudaDeviceGetAttribute(&nsm, cudaDevAttrMultiProcessorCount, 0);
    if (nsm <= 0 || nsm > NTILES) nsm = 148;

    cudaFuncSetAttribute(gemm_node_tc, cudaFuncAttributeMaxDynamicSharedMemorySize, GN_SMEM);
    cudaFuncSetAttribute(edge_score_mma, cudaFuncAttributeMaxDynamicSharedMemorySize, ES_SMEM_BYTES);

    const int gemm_blocks = (NSRC + 127) / 128;
    const int scan_blocks = (NDST + 1023) / 1024;

    // 1. node projections (HMMA split)
    gemm_node_tc<<<gemm_blocks, 256, GN_SMEM>>>(feat_src, W_src, b_src, hs_p, NSRC, 0);
    gemm_node_tc<<<gemm_blocks, 256, GN_SMEM>>>(feat_dst, W_dst, b_dst, hd_p, NDST, 0);

    // 2. CSR build (edges grouped by dst)
    k_zero<<<(NDST + 255) / 256, 256>>>();
    k_hist<<<(NEDGE + 255) / 256, 256>>>(dst_idx);
    k_scan1<<<scan_blocks, 1024>>>();
    k_scan2<<<1, 64>>>(scan_blocks);
    k_scan3<<<scan_blocks, 1024>>>();
    k_scatter<<<(NEDGE + 255) / 256, 256>>>(dst_idx);

    // 3. per-edge attention scores via HMMA (persistent, pipelined)
    edge_score_mma<<<nsm, 256, ES_SMEM_BYTES>>>(src_idx, dst_idx, W_a1, b_a1, W_a2, b_a2);

    // 4. segment softmax + weighted aggregation
    k_aggregate<<<(NDST * 32 + 255) / 256, 256>>>(src_idx);

    // 5. output projection + leaky relu -> d_out
    gemm_node_tc<<<gemm_blocks, 256, GN_SMEM>>>(nf_p, W_out, b_out, out, NDST, 1);
}

// round 11
// speedup vs baseline: 1.7536x; 1.0276x over previous
#include <cuda_runtime.h>
#include <cuda_bf16.h>
#include <cstdint>

#define D 128
#define NSRC 50000
#define NDST 50000
#define NEDGE 640000
#define NTILES (NEDGE / 128)
#define NEG_SLOPE 0.01f

// ---------------- device scratch (static, no allocation) ----------------
__device__ float g_hs[NSRC * D];
__device__ float g_hd[NDST * D];
__device__ float g_nf[NDST * D];
__device__ float g_score[NEDGE];   // CSR-permuted scores
__device__ int g_srcp[NEDGE];      // CSR-permuted src indices
__device__ int g_epos[NEDGE];      // edge -> CSR slot
__device__ int g_count[NDST];
__device__ int g_offset[NDST + 1];
__device__ int g_cursor[NDST];
__device__ int g_bsums[64];
__device__ int g_bsums2[64];

__device__ __forceinline__ float lrelu(float x) { return x > 0.f ? x : NEG_SLOPE * x; }

// Swizzled element offset inside a [128 rows x 128 cols] bf16 tile.
__device__ __forceinline__ uint32_t swz_off(int r, int c) {
    return (uint32_t)((r << 7) + ((((c >> 3) ^ (r & 7)) << 3) + (c & 7)));
}

__device__ __forceinline__ uint32_t smem_u32(const void* p) {
    uint32_t a;
    asm("{ .reg .u64 t; cvta.to.shared.u64 t, %1; cvt.u32.u64 %0, t; }" : "=r"(a) : "l"(p));
    return a;
}

#define LDSM_X4(r0, r1, r2, r3, addr) \
    asm volatile("ldmatrix.sync.aligned.m8n8.x4.shared.b16 {%0,%1,%2,%3}, [%4];" \
        : "=r"(r0), "=r"(r1), "=r"(r2), "=r"(r3) : "r"(addr))
#define LDSM_X4_T(r0, r1, r2, r3, addr) \
    asm volatile("ldmatrix.sync.aligned.m8n8.x4.trans.shared.b16 {%0,%1,%2,%3}, [%4];" \
        : "=r"(r0), "=r"(r1), "=r"(r2), "=r"(r3) : "r"(addr))
#define MMA_BF16(c0, c1, c2, c3, a0, a1, a2, a3, b0, b1) \
    asm volatile("mma.sync.aligned.m16n8k16.row.col.f32.bf16.bf16.f32 " \
        "{%0,%1,%2,%3}, {%4,%5,%6,%7}, {%8,%9}, {%0,%1,%2,%3};" \
        : "+f"(c0), "+f"(c1), "+f"(c2), "+f"(c3) \
        : "r"(a0), "r"(a1), "r"(a2), "r"(a3), "r"(b0), "r"(b1))

__device__ __forceinline__ void split2(float t0, float t1, uint32_t& hi, uint32_t& lo) {
    asm("cvt.rn.bf16x2.f32 %0, %1, %2;" : "=r"(hi) : "f"(t1), "f"(t0));
    float h0 = __uint_as_float(hi << 16);
    float h1 = __uint_as_float(hi & 0xffff0000u);
    asm("cvt.rn.bf16x2.f32 %0, %1, %2;" : "=r"(lo) : "f"(t1 - h1), "f"(t0 - h0));
}

// =======================================================================
// Node GEMM via HMMA (3-term bf16 split) — unchanged, proven.
// =======================================================================
#define GN_SMEM (128 * 1024 + 512)

__global__ __launch_bounds__(256, 1)
void gemm_node_tc(const float* __restrict__ A, const float* __restrict__ W,
                  const float* __restrict__ bias, float* __restrict__ Out,
                  int nrows, int act)
{
    extern __shared__ float smem[];
    char* smc = (char*)smem;
    char* sWB_hi = smc;
    char* sWB_lo = smc + 32768;
    char* sAB_hi = smc + 65536;
    char* sAB_lo = smc + 98304;
    float* sbias = (float*)(smc + 131072);

    const int tid = threadIdx.x;
    const int wid = tid >> 5;
    const int lane = tid & 31;
    const int row0 = blockIdx.x * 128;

    for (int i = tid; i < D * D; i += 256) {
        int k = i >> 7, n = i & 127;
        float v = W[i];
        __nv_bfloat16 hi = __float2bfloat16(v);
        float lo = v - __bfloat162float(hi);
        uint32_t off = swz_off(k, n);
        ((__nv_bfloat16*)sWB_hi)[off] = hi;
        ((__nv_bfloat16*)sWB_lo)[off] = __float2bfloat16(lo);
    }
    {
        const float4* A4 = (const float4*)A;
#pragma unroll 4
        for (int it = 0; it < 16; ++it) {
            int idx = it * 256 + tid;
            int r = idx >> 5, c4 = idx & 31;
            int gr = row0 + r;
            float4 v = make_float4(0.f, 0.f, 0.f, 0.f);
            if (gr < nrows) v = A4[gr * 32 + c4];
            uint32_t hi01, lo01, hi23, lo23;
            split2(v.x, v.y, hi01, lo01);
            split2(v.z, v.w, hi23, lo23);
            uint32_t off = swz_off(r, c4 * 4) * 2;
            *(uint2*)(sAB_hi + off) = make_uint2(hi01, hi23);
            *(uint2*)(sAB_lo + off) = make_uint2(lo01, lo23);
        }
    }
    if (tid < 128) sbias[tid] = bias[tid];
    __syncthreads();

    const int rg = wid & 3, cg = wid >> 2;
    const int row_lo = (lane & 7) + ((lane >> 3) & 1) * 8;
    const int acg = (lane >> 4) & 1;
    const int x7 = lane & 7;
    const int g = lane >> 2;
    const int tig = lane & 3;
    const uint32_t sA_hi_b = smem_u32(sAB_hi);
    const uint32_t sA_lo_b = smem_u32(sAB_lo);
    const uint32_t sB_hi_b = smem_u32(sWB_hi);
    const uint32_t sB_lo_b = smem_u32(sWB_lo);

    float acc[2][8][4];
#pragma unroll
    for (int rc = 0; rc < 2; ++rc)
#pragma unroll
        for (int np = 0; np < 8; ++np)
#pragma unroll
            for (int j = 0; j < 4; ++j) acc[rc][np][j] = 0.f;

#pragma unroll
    for (int ks = 0; ks < 8; ++ks) {
        uint32_t ah[2][4], al[2][4];
#pragma unroll
        for (int rc = 0; rc < 2; ++rc) {
            uint32_t a_off = (uint32_t)((rg * 32 + rc * 16 + row_lo) << 8)
                           + (uint32_t)((((2 * ks + acg) ^ x7) << 4));
            LDSM_X4(ah[rc][0], ah[rc][1], ah[rc][2], ah[rc][3], sA_hi_b + a_off);
            LDSM_X4(al[rc][0], al[rc][1], al[rc][2], al[rc][3], sA_lo_b + a_off);
        }
        const int bk = ks * 16 + row_lo;
#pragma unroll
        for (int p = 0; p < 4; ++p) {
            int cidx = 2 * (cg * 4 + p) + acg;
            uint32_t b_off = (uint32_t)(bk << 8) + (uint32_t)(((cidx ^ x7) << 4));
            uint32_t bh0, bh1, bh2, bh3, bl0, bl1, bl2, bl3;
            LDSM_X4_T(bh0, bh1, bh2, bh3, sB_hi_b + b_off);
            LDSM_X4_T(bl0, bl1, bl2, bl3, sB_lo_b + b_off);
#pragma unroll
            for (int rc = 0; rc < 2; ++rc) {
                float* c0 = acc[rc][2 * p];
                float* c1 = acc[rc][2 * p + 1];
                MMA_BF16(c0[0], c0[1], c0[2], c0[3], ah[rc][0], ah[rc][1], ah[rc][2], ah[rc][3], bh0, bh1);
                MMA_BF16(c0[0], c0[1], c0[2], c0[3], al[rc][0], al[rc][1], al[rc][2], al[rc][3], bh0, bh1);
                MMA_BF16(c0[0], c0[1], c0[2], c0[3], ah[rc][0], ah[rc][1], ah[rc][2], ah[rc][3], bl0, bl1);
                MMA_BF16(c1[0], c1[1], c1[2], c1[3], ah[rc][0], ah[rc][1], ah[rc][2], ah[rc][3], bh2, bh3);
                MMA_BF16(c1[0], c1[1], c1[2], c1[3], al[rc][0], al[rc][1], al[rc][2], al[rc][3], bh2, bh3);
                MMA_BF16(c1[0], c1[1], c1[2], c1[3], ah[rc][0], ah[rc][1], ah[rc][2], ah[rc][3], bl2, bl3);
            }
        }
    }

#pragma unroll
    for (int rc = 0; rc < 2; ++rc) {
#pragma unroll
        for (int np = 0; np < 8; ++np) {
            int n = cg * 64 + np * 8 + tig * 2;
            float b0 = sbias[n], b1 = sbias[n + 1];
            int r1 = row0 + rg * 32 + rc * 16 + g;
            float v0 = acc[rc][np][0] + b0, v1 = acc[rc][np][1] + b1;
            float v2 = acc[rc][np][2] + b0, v3 = acc[rc][np][3] + b1;
            if (act) { v0 = lrelu(v0); v1 = lrelu(v1); v2 = lrelu(v2); v3 = lrelu(v3); }
            if (r1 < nrows) *(float2*)(Out + r1 * 128 + n) = make_float2(v0, v1);
            if (r1 + 8 < nrows) *(float2*)(Out + (r1 + 8) * 128 + n) = make_float2(v2, v3);
        }
    }
}

// =======================================================================
// Edge scoring via HMMA, software-pipelined:
// per chunk: (L) LDG next tile's data into regs, (M) 2 k-steps of
// LDSM+HMMA (independent of L), (S) convert+STS into next buffer.
// Scores written directly into CSR-permuted g_score via g_epos.
// =======================================================================
#define ES_SMEM_BYTES 198656

__device__ __forceinline__ void gather_direct(
    const int* __restrict__ src_idx, const int* __restrict__ dst_idx,
    int e0, char* a_hi, char* a_lo, int tid)
{
    const float4* hs4 = (const float4*)g_hs;
    const float4* hd4 = (const float4*)g_hd;
#pragma unroll 4
    for (int it = 0; it < 16; ++it) {
        int idx = it * 256 + tid;
        int r = idx >> 5, c4 = idx & 31;
        int e = e0 + r;
        int si = __ldg(&src_idx[e]);
        int di = __ldg(&dst_idx[e]);
        float4 u = hs4[si * 32 + c4];
        float4 v = hd4[di * 32 + c4];
        float t0 = lrelu(u.x + v.x), t1 = lrelu(u.y + v.y);
        float t2 = lrelu(u.z + v.z), t3 = lrelu(u.w + v.w);
        uint32_t hi01, lo01, hi23, lo23;
        split2(t0, t1, hi01, lo01);
        split2(t2, t3, hi23, lo23);
        uint32_t off = swz_off(r, c4 * 4) * 2;
        *(uint2*)(a_hi + off) = make_uint2(hi01, hi23);
        *(uint2*)(a_lo + off) = make_uint2(lo01, lo23);
    }
}

__global__ __launch_bounds__(256, 1)
void edge_score_mma(const int* __restrict__ src_idx, const int* __restrict__ dst_idx,
                    const float* __restrict__ Wa1, const float* __restrict__ ba1,
                    const float* __restrict__ Wa2, const float* __restrict__ ba2)
{
    extern __shared__ float smem[];
    char* smc = (char*)smem;
    char* sB_hi = smc;
    char* sB_lo = smc + 32768;
    char* sA_base = smc + 65536;       // 2 bufs x (hi 32KB + lo 32KB)
    float* sb1 = (float*)(smc + 196608);
    float* sw2 = (float*)(smc + 197120);
    float* sRed = (float*)(smc + 197632);  // 128 x 2

    const int tid = threadIdx.x;
    const int wid = tid >> 5;
    const int lane = tid & 31;

    for (int i = tid; i < D * D; i += 256) {
        int k = i >> 7, n = i & 127;
        float v = Wa1[i];
        __nv_bfloat16 hi = __float2bfloat16(v);
        float lo = v - __bfloat162float(hi);
        uint32_t off = swz_off(k, n);
        ((__nv_bfloat16*)sB_hi)[off] = hi;
        ((__nv_bfloat16*)sB_lo)[off] = __float2bfloat16(lo);
    }
    if (tid < 128) { sb1[tid] = ba1[tid]; sw2[tid] = Wa2[tid]; }

    const float bias2 = ba2[0];
    const int rg = wid & 3, cg = wid >> 2;
    const int row_lo = (lane & 7) + ((lane >> 3) & 1) * 8;
    const int acg = (lane >> 4) & 1;
    const int x7 = lane & 7;
    const int g = lane >> 2;
    const int tig = lane & 3;
    const uint32_t sB_hi_b = smem_u32(sB_hi);
    const uint32_t sB_lo_b = smem_u32(sB_lo);
    const uint32_t sA_b = smem_u32(sA_base);

    const float4* hs4 = (const float4*)g_hs;
    const float4* hd4 = (const float4*)g_hd;

    const int bid = blockIdx.x;
    const int grid = gridDim.x;

    // prefill buffer 0 with first tile
    if (bid < NTILES)
        gather_direct(src_idx, dst_idx, bid * 128, sA_base, sA_base + 32768, tid);
    __syncthreads();

    // invariant per-thread gather geometry: r = chunk-local; this thread always
    // handles rows rbase(+its iter) col group c4
    const int c4 = tid & 31;        // float4 column index 0..31
    const int rsub = tid >> 5;      // 0..7: row within each 32-row chunk block

    int buf = 0;
    for (int tile = bid; tile < NTILES; tile += grid) {
        const int nxt = tile + grid;
        const uint32_t cur_hi = sA_b + (uint32_t)buf * 65536u;
        const uint32_t cur_lo = cur_hi + 32768u;
        char* nxt_hi = sA_base + (buf ^ 1) * 65536;
        char* nxt_lo = nxt_hi + 32768;
        const bool have_nxt = (nxt < NTILES);
        const int ne0 = nxt * 128;

        float acc[2][8][4];
#pragma unroll
        for (int rc = 0; rc < 2; ++rc)
#pragma unroll
            for (int np = 0; np < 8; ++np)
#pragma unroll
                for (int j = 0; j < 4; ++j) acc[rc][np][j] = 0.f;

#pragma unroll
        for (int c = 0; c < 4; ++c) {
            // ---- L: issue next tile's loads into registers (no smem dep) ----
            float4 pu[4], pv[4];
            if (have_nxt) {
#pragma unroll
                for (int q = 0; q < 4; ++q) {
                    int r = c * 32 + q * 8 + rsub;
                    int e = ne0 + r;
                    int si = __ldg(&src_idx[e]);
                    int di = __ldg(&dst_idx[e]);
                    pu[q] = hs4[si * 32 + c4];
                    pv[q] = hd4[di * 32 + c4];
                }
            }

            // ---- M: 2 k-steps of MMA on current buffer ----
#pragma unroll
            for (int ksi = 0; ksi < 2; ++ksi) {
                const int ks = 2 * c + ksi;
                uint32_t ah[2][4], al[2][4];
#pragma unroll
                for (int rc = 0; rc < 2; ++rc) {
                    uint32_t a_off = (uint32_t)((rg * 32 + rc * 16 + row_lo) << 8)
                                   + (uint32_t)((((2 * ks + acg) ^ x7) << 4));
                    LDSM_X4(ah[rc][0], ah[rc][1], ah[rc][2], ah[rc][3], cur_hi + a_off);
                    LDSM_X4(al[rc][0], al[rc][1], al[rc][2], al[rc][3], cur_lo + a_off);
                }
                const int bk = ks * 16 + row_lo;
#pragma unroll
                for (int p = 0; p < 4; ++p) {
                    int cidx = 2 * (cg * 4 + p) + acg;
                    uint32_t b_off = (uint32_t)(bk << 8) + (uint32_t)(((cidx ^ x7) << 4));
                    uint32_t bh0, bh1, bh2, bh3, bl0, bl1, bl2, bl3;
                    LDSM_X4_T(bh0, bh1, bh2, bh3, sB_hi_b + b_off);
                    LDSM_X4_T(bl0, bl1, bl2, bl3, sB_lo_b + b_off);
#pragma unroll
                    for (int rc = 0; rc < 2; ++rc) {
                        float* c0 = acc[rc][2 * p];
                        float* c1 = acc[rc][2 * p + 1];
                        MMA_BF16(c0[0], c0[1], c0[2], c0[3], ah[rc][0], ah[rc][1], ah[rc][2], ah[rc][3], bh0, bh1);
                        MMA_BF16(c0[0], c0[1], c0[2], c0[3], al[rc][0], al[rc][1], al[rc][2], al[rc][3], bh0, bh1);
                        MMA_BF16(c0[0], c0[1], c0[2], c0[3], ah[rc][0], ah[rc][1], ah[rc][2], ah[rc][3], bl0, bl1);
                        MMA_BF16(c1[0], c1[1], c1[2], c1[3], ah[rc][0], ah[rc][1], ah[rc][2], ah[rc][3], bh2, bh3);
                        MMA_BF16(c1[0], c1[1], c1[2], c1[3], al[rc][0], al[rc][1], al[rc][2], al[rc][3], bh2, bh3);
                        MMA_BF16(c1[0], c1[1], c1[2], c1[3], ah[rc][0], ah[rc][1], ah[rc][2], ah[rc][3], bl2, bl3);
                    }
                }
            }

            // ---- S: convert + store next tile chunk (LDG latency now hidden) ----
            if (have_nxt) {
#pragma unroll
                for (int q = 0; q < 4; ++q) {
                    int r = c * 32 + q * 8 + rsub;
                    float t0 = lrelu(pu[q].x + pv[q].x), t1 = lrelu(pu[q].y + pv[q].y);
                    float t2 = lrelu(pu[q].z + pv[q].z), t3 = lrelu(pu[q].w + pv[q].w);
                    uint32_t hi01, lo01, hi23, lo23;
                    split2(t0, t1, hi01, lo01);
                    split2(t2, t3, hi23, lo23);
                    uint32_t off = swz_off(r, c4 * 4) * 2;
                    *(uint2*)(nxt_hi + off) = make_uint2(hi01, hi23);
                    *(uint2*)(nxt_lo + off) = make_uint2(lo01, lo23);
                }
            }
        }

        // ---- epilogue: per-warp partial dot over its 64 cols ----
#pragma unroll
        for (int rc = 0; rc < 2; ++rc) {
            float p0 = 0.f, p1 = 0.f;
#pragma unroll
            for (int np = 0; np < 8; ++np) {
                int n = cg * 64 + np * 8 + tig * 2;
                float b0 = sb1[n], b1 = sb1[n + 1];
                float w0 = sw2[n], w1 = sw2[n + 1];
                p0 += lrelu(acc[rc][np][0] + b0) * w0 + lrelu(acc[rc][np][1] + b1) * w1;
                p1 += lrelu(acc[rc][np][2] + b0) * w0 + lrelu(acc[rc][np][3] + b1) * w1;
            }
            p0 += __shfl_xor_sync(0xffffffffu, p0, 1);
            p0 += __shfl_xor_sync(0xffffffffu, p0, 2);
            p1 += __shfl_xor_sync(0xffffffffu, p1, 1);
            p1 += __shfl_xor_sync(0xffffffffu, p1, 2);
            if (tig == 0) {
                int row = rg * 32 + rc * 16 + g;
                sRed[row * 2 + cg] = p0;
                sRed[(row + 8) * 2 + cg] = p1;
            }
        }
        __syncthreads();   // sRed ready; next A buf fully written; cur reads done
        if (tid < 128) {
            int slot = __ldg(&g_epos[tile * 128 + tid]);
            g_score[slot] = sRed[tid * 2] + sRed[tid * 2 + 1] + bias2;
        }
        __syncthreads();   // protect sRed
        buf ^= 1;
    }
}

// ---------------- CSR build: count / scan / scatter ----------------
__global__ void k_zero()
{
    int i = blockIdx.x * 256 + threadIdx.x;
    if (i < NDST) { g_count[i] = 0; g_cursor[i] = 0; }
}

__global__ void k_hist(const int* __restrict__ dst_idx)
{
    int e = blockIdx.x * 256 + threadIdx.x;
    if (e < NEDGE) atomicAdd(&g_count[dst_idx[e]], 1);
}

__global__ void k_scan1()
{
    int tid = threadIdx.x;
    int gid = blockIdx.x * 1024 + tid;
    int v = (gid < NDST) ? g_count[gid] : 0;
    int lane = tid & 31, w = tid >> 5;
    int x = v;
#pragma unroll
    for (int o = 1; o < 32; o <<= 1) {
        int y = __shfl_up_sync(0xffffffffu, x, o);
        if (lane >= o) x += y;
    }
    __shared__ int ws[32];
    if (lane == 31) ws[w] = x;
    __syncthreads();
    if (w == 0) {
        int y = ws[lane];
#pragma unroll
        for (int o = 1; o < 32; o <<= 1) {
            int z = __shfl_up_sync(0xffffffffu, y, o);
            if (lane >= o) y += z;
        }
        ws[lane] = y;
    }
    __syncthreads();
    int pref = (w > 0) ? ws[w - 1] : 0;
    int incl = x + pref;
    if (gid < NDST) g_offset[gid] = incl - v;
    if (tid == 1023) g_bsums[blockIdx.x] = incl;
}

__global__ void k_scan2(int nblocks)
{
    int tid = threadIdx.x;
    int v = (tid < nblocks) ? g_bsums[tid] : 0;
    int lane = tid & 31, w = tid >> 5;
    int x = v;
#pragma unroll
    for (int o = 1; o < 32; o <<= 1) {
        int y = __shfl_up_sync(0xffffffffu, x, o);
        if (lane >= o) x += y;
    }
    __shared__ int ws[2];
    if (lane == 31) ws[w] = x;
    __syncthreads();
    if (w == 1) x += ws[0];
    g_bsums2[tid] = x - v;
}

__global__ void k_scan3()
{
    int gid = blockIdx.x * 1024 + threadIdx.x;
    if (gid < NDST) g_offset[gid] += g_bsums2[blockIdx.x];
    if (gid == 0) g_offset[NDST] = NEDGE;
}

__global__ void k_scatter(const int* __restrict__ dst_idx, const int* __restrict__ src_idx)
{
    int e = blockIdx.x * 256 + threadIdx.x;
    if (e < NEDGE) {
        int d = dst_idx[e];
        int p = atomicAdd(&g_cursor[d], 1);
        int slot = g_offset[d] + p;
        g_epos[e] = slot;
        g_srcp[slot] = src_idx[e];
    }
}

// ---------------- softmax + aggregate: one warp per dst, contiguous reads ----
__global__ void k_aggregate()
{
    int gw = (blockIdx.x * blockDim.x + threadIdx.x) >> 5;
    int lane = threadIdx.x & 31;
    if (gw >= NDST) return;
    int beg = g_offset[gw], end = g_offset[gw + 1];

    const float4* hs4 = (const float4*)g_hs;
    const float4* hd4 = (const float4*)g_hd;
    float4 acc = make_float4(0.f, 0.f, 0.f, 0.f);

    if (end > beg) {
        float m = __int_as_float(0xff800000);
        for (int i = beg + lane; i < end; i += 32)
            m = fmaxf(m, g_score[i]);
#pragma unroll
        for (int o = 16; o; o >>= 1) m = fmaxf(m, __shfl_xor_sync(0xffffffffu, m, o));

        float dsum = 0.f;
        for (int i = beg + lane; i < end; i += 32)
            dsum += __expf(g_score[i] - m);
#pragma unroll
        for (int o = 16; o; o >>= 1) dsum += __shfl_xor_sync(0xffffffffu, dsum, o);
        float inv = 1.f / dsum;

        // weighted gather with one-ahead prefetch of src/score
        int s_nx = g_srcp[beg];
        float sc_nx = g_score[beg];
        for (int i = beg; i < end; ++i) {
            int s = s_nx;
            float sc = sc_nx;
            if (i + 1 < end) { s_nx = g_srcp[i + 1]; sc_nx = g_score[i + 1]; }
            float w = __expf(sc - m) * inv;
            float4 h = hs4[s * 32 + lane];
            acc.x += w * h.x; acc.y += w * h.y; acc.z += w * h.z; acc.w += w * h.w;
        }
        float4 hv = hd4[gw * 32 + lane];
        acc.x += hv.x; acc.y += hv.y; acc.z += hv.z; acc.w += hv.w;
    }
    ((float4*)g_nf)[gw * 32 + lane] = acc;
}

// ---------------- launch ----------------
extern "C" void kernel_launch(void* const* d_in, const int* in_sizes, int n_in,
                              void* d_out, int out_size)
{
    const float* feat_src = (const float*)d_in[0];
    const float* feat_dst = (const float*)d_in[1];
    const int*   src_idx  = (const int*)d_in[2];
    const int*   dst_idx  = (const int*)d_in[3];
    const float* W_src = (const float*)d_in[4];
    const float* b_src = (const float*)d_in[5];
    const float* W_dst = (const float*)d_in[6];
    const float* b_dst = (const float*)d_in[7];
    const float* W_a1  = (const float*)d_in[8];
    const float* b_a1  = (const float*)d_in[9];
    const float* W_a2  = (const float*)d_in[10];
    const float* b_a2  = (const float*)d_in[11];
    const float* W_out = (const float*)d_in[12];
    const float* b_out = (const float*)d_in[13];
    float* out = (float*)d_out;

    float *hs_p, *hd_p, *nf_p;
    cudaGetSymbolAddress((void**)&hs_p, g_hs);
    cudaGetSymbolAddress((void**)&hd_p, g_hd);
    cudaGetSymbolAddress((void**)&nf_p, g_nf);

    int nsm = 148;
    cudaDeviceGetAttribute(&nsm, cudaDevAttrMultiProcessorCount, 0);
    if (nsm <= 0 || nsm > NTILES) nsm = 148;

    cudaFuncSetAttribute(gemm_node_tc, cudaFuncAttributeMaxDynamicSharedMemorySize, GN_SMEM);
    cudaFuncSetAttribute(edge_score_mma, cudaFuncAttributeMaxDynamicSharedMemorySize, ES_SMEM_BYTES);

    const int gemm_blocks = (NSRC + 127) / 128;
    const int scan_blocks = (NDST + 1023) / 1024;

    // 1. node projections (HMMA split)
    gemm_node_tc<<<gemm_blocks, 256, GN_SMEM>>>(feat_src, W_src, b_src, hs_p, NSRC, 0);
    gemm_node_tc<<<gemm_blocks, 256, GN_SMEM>>>(feat_dst, W_dst, b_dst, hd_p, NDST, 0);

    // 2. CSR build (produces g_epos / g_srcp)
    k_zero<<<(NDST + 255) / 256, 256>>>();
    k_hist<<<(NEDGE + 255) / 256, 256>>>(dst_idx);
    k_scan1<<<scan_blocks, 1024>>>();
    k_scan2<<<1, 64>>>(scan_blocks);
    k_scan3<<<scan_blocks, 1024>>>();
    k_scatter<<<(NEDGE + 255) / 256, 256>>>(dst_idx, src_idx);

    // 3. per-edge attention scores via HMMA (persistent, pipelined)
    edge_score_mma<<<nsm, 256, ES_SMEM_BYTES>>>(src_idx, dst_idx, W_a1, b_a1, W_a2, b_a2);

    // 4. segment softmax + weighted aggregation (contiguous)
    k_aggregate<<<(NDST * 32 + 255) / 256, 256>>>();

    // 5. output projection + leaky relu -> d_out
    gemm_node_tc<<<gemm_blocks, 256, GN_SMEM>>>(nf_p, W_out, b_out, out, NDST, 1);
}

// round 13
// speedup vs baseline: 2.2199x; 1.2659x over previous
#include <cuda_runtime.h>
#include <cuda_fp16.h>
#include <cstdint>

#define D 128
#define NSRC 50000
#define NDST 50000
#define NEDGE 640000
#define NTILES (NEDGE / 128)
#define NEG_SLOPE 0.01f

// ---------------- device scratch (static, no allocation) ----------------
__device__ float g_hs[NSRC * D];
__device__ float g_hd[NDST * D];
__device__ float g_nf[NDST * D];
__device__ float g_score[NEDGE];   // CSR-permuted scores
__device__ int g_srcp[NEDGE];      // CSR-permuted src indices
__device__ int g_epos[NEDGE];      // edge -> CSR slot
__device__ int g_count[NDST];
__device__ int g_offset[NDST + 1];
__device__ int g_cursor[NDST];
__device__ int g_bsums[64];
__device__ int g_bsums2[64];

__device__ __forceinline__ float lrelu(float x) { return x > 0.f ? x : NEG_SLOPE * x; }

// Swizzled element offset inside a [128 rows x 128 cols] f16 tile.
__device__ __forceinline__ uint32_t swz_off(int r, int c) {
    return (uint32_t)((r << 7) + ((((c >> 3) ^ (r & 7)) << 3) + (c & 7)));
}

__device__ __forceinline__ uint32_t smem_u32(const void* p) {
    uint32_t a;
    asm("{ .reg .u64 t; cvta.to.shared.u64 t, %1; cvt.u32.u64 %0, t; }" : "=r"(a) : "l"(p));
    return a;
}

#define LDSM_X4(r0, r1, r2, r3, addr) \
    asm volatile("ldmatrix.sync.aligned.m8n8.x4.shared.b16 {%0,%1,%2,%3}, [%4];" \
        : "=r"(r0), "=r"(r1), "=r"(r2), "=r"(r3) : "r"(addr))
#define LDSM_X4_T(r0, r1, r2, r3, addr) \
    asm volatile("ldmatrix.sync.aligned.m8n8.x4.trans.shared.b16 {%0,%1,%2,%3}, [%4];" \
        : "=r"(r0), "=r"(r1), "=r"(r2), "=r"(r3) : "r"(addr))
#define MMA_F16(c0, c1, c2, c3, a0, a1, a2, a3, b0, b1) \
    asm volatile("mma.sync.aligned.m16n8k16.row.col.f32.f16.f16.f32 " \
        "{%0,%1,%2,%3}, {%4,%5,%6,%7}, {%8,%9}, {%0,%1,%2,%3};" \
        : "+f"(c0), "+f"(c1), "+f"(c2), "+f"(c3) \
        : "r"(a0), "r"(a1), "r"(a2), "r"(a3), "r"(b0), "r"(b1))

// split two fp32 into fp16 hi pair + fp16 residual pair (packed f16x2 words)
__device__ __forceinline__ void split2h(float t0, float t1, uint32_t& hi, uint32_t& lo) {
    __half2 h = __floats2half2_rn(t0, t1);
    float h0 = __low2float(h), h1 = __high2float(h);
    __half2 l = __floats2half2_rn(t0 - h0, t1 - h1);
    hi = *reinterpret_cast<uint32_t*>(&h);
    lo = *reinterpret_cast<uint32_t*>(&l);
}

// =======================================================================
// Node GEMM via HMMA (2-term fp16: A hi+lo, W single fp16).
// SMEM: sW 32KB | sA_hi 32KB | sA_lo 32KB | bias 512B  => 2 CTAs/SM.
// =======================================================================
#define GN_SMEM (96 * 1024 + 512)

__device__ __forceinline__ void gemm_node_body(
    const float* __restrict__ A, const float* __restrict__ W,
    const float* __restrict__ bias, float* __restrict__ Out,
    int nrows, int act, int blk, char* smc)
{
    char* sW    = smc;
    char* sA_hi = smc + 32768;
    char* sA_lo = smc + 65536;
    float* sbias = (float*)(smc + 98304);

    const int tid = threadIdx.x;
    const int wid = tid >> 5;
    const int lane = tid & 31;
    const int row0 = blk * 128;

    for (int i = tid; i < D * D; i += 256) {
        int k = i >> 7, n = i & 127;
        ((__half*)sW)[swz_off(k, n)] = __float2half_rn(W[i]);
    }
    {
        const float4* A4 = (const float4*)A;
#pragma unroll 4
        for (int it = 0; it < 16; ++it) {
            int idx = it * 256 + tid;
            int r = idx >> 5, c4 = idx & 31;
            int gr = row0 + r;
            float4 v = make_float4(0.f, 0.f, 0.f, 0.f);
            if (gr < nrows) v = A4[gr * 32 + c4];
            uint32_t hi01, lo01, hi23, lo23;
            split2h(v.x, v.y, hi01, lo01);
            split2h(v.z, v.w, hi23, lo23);
            uint32_t off = swz_off(r, c4 * 4) * 2;
            *(uint2*)(sA_hi + off) = make_uint2(hi01, hi23);
            *(uint2*)(sA_lo + off) = make_uint2(lo01, lo23);
        }
    }
    if (tid < 128) sbias[tid] = bias[tid];
    __syncthreads();

    const int rg = wid & 3, cg = wid >> 2;
    const int row_lo = (lane & 7) + ((lane >> 3) & 1) * 8;
    const int acg = (lane >> 4) & 1;
    const int x7 = lane & 7;
    const int g = lane >> 2;
    const int tig = lane & 3;
    const uint32_t sA_hi_b = smem_u32(sA_hi);
    const uint32_t sA_lo_b = smem_u32(sA_lo);
    const uint32_t sW_b = smem_u32(sW);

    float acc[2][8][4];
#pragma unroll
    for (int rc = 0; rc < 2; ++rc)
#pragma unroll
        for (int np = 0; np < 8; ++np)
#pragma unroll
            for (int j = 0; j < 4; ++j) acc[rc][np][j] = 0.f;

#pragma unroll
    for (int ks = 0; ks < 8; ++ks) {
        uint32_t ah[2][4], al[2][4];
#pragma unroll
        for (int rc = 0; rc < 2; ++rc) {
            uint32_t a_off = (uint32_t)((rg * 32 + rc * 16 + row_lo) << 8)
                           + (uint32_t)((((2 * ks + acg) ^ x7) << 4));
            LDSM_X4(ah[rc][0], ah[rc][1], ah[rc][2], ah[rc][3], sA_hi_b + a_off);
            LDSM_X4(al[rc][0], al[rc][1], al[rc][2], al[rc][3], sA_lo_b + a_off);
        }
        const int bk = ks * 16 + row_lo;
#pragma unroll
        for (int p = 0; p < 4; ++p) {
            int cidx = 2 * (cg * 4 + p) + acg;
            uint32_t b_off = (uint32_t)(bk << 8) + (uint32_t)(((cidx ^ x7) << 4));
            uint32_t bh0, bh1, bh2, bh3;
            LDSM_X4_T(bh0, bh1, bh2, bh3, sW_b + b_off);
#pragma unroll
            for (int rc = 0; rc < 2; ++rc) {
                float* c0 = acc[rc][2 * p];
                float* c1 = acc[rc][2 * p + 1];
                MMA_F16(c0[0], c0[1], c0[2], c0[3], ah[rc][0], ah[rc][1], ah[rc][2], ah[rc][3], bh0, bh1);
                MMA_F16(c0[0], c0[1], c0[2], c0[3], al[rc][0], al[rc][1], al[rc][2], al[rc][3], bh0, bh1);
                MMA_F16(c1[0], c1[1], c1[2], c1[3], ah[rc][0], ah[rc][1], ah[rc][2], ah[rc][3], bh2, bh3);
                MMA_F16(c1[0], c1[1], c1[2], c1[3], al[rc][0], al[rc][1], al[rc][2], al[rc][3], bh2, bh3);
            }
        }
    }

#pragma unroll
    for (int rc = 0; rc < 2; ++rc) {
#pragma unroll
        for (int np = 0; np < 8; ++np) {
            int n = cg * 64 + np * 8 + tig * 2;
            float b0 = sbias[n], b1 = sbias[n + 1];
            int r1 = row0 + rg * 32 + rc * 16 + g;
            float v0 = acc[rc][np][0] + b0, v1 = acc[rc][np][1] + b1;
            float v2 = acc[rc][np][2] + b0, v3 = acc[rc][np][3] + b1;
            if (act) { v0 = lrelu(v0); v1 = lrelu(v1); v2 = lrelu(v2); v3 = lrelu(v3); }
            if (r1 < nrows) *(float2*)(Out + r1 * 128 + n) = make_float2(v0, v1);
            if (r1 + 8 < nrows) *(float2*)(Out + (r1 + 8) * 128 + n) = make_float2(v2, v3);
        }
    }
}

__global__ __launch_bounds__(256, 2)
void gemm_node_tc(const float* __restrict__ A, const float* __restrict__ W,
                  const float* __restrict__ bias, float* __restrict__ Out,
                  int nrows, int act)
{
    extern __shared__ float smem[];
    gemm_node_body(A, W, bias, Out, nrows, act, blockIdx.x, (char*)smem);
}

// fused src+dst projections: blocks [0, nb) -> src, [nb, 2nb) -> dst
__global__ __launch_bounds__(256, 2)
void gemm_node_dual(const float* __restrict__ A0, const float* __restrict__ W0,
                    const float* __restrict__ b0, float* __restrict__ O0,
                    const float* __restrict__ A1, const float* __restrict__ W1,
                    const float* __restrict__ b1, float* __restrict__ O1,
                    int nrows, int nb)
{
    extern __shared__ float smem[];
    if (blockIdx.x < nb)
        gemm_node_body(A0, W0, b0, O0, nrows, 0, blockIdx.x, (char*)smem);
    else
        gemm_node_body(A1, W1, b1, O1, nrows, 0, blockIdx.x - nb, (char*)smem);
}

// =======================================================================
// Edge scoring via HMMA, 2-term fp16, software-pipelined.
// SMEM: sW 32KB | sA 2 bufs x (hi 32KB + lo 32KB) | sb1 | sw2 | sRed
// =======================================================================
#define ES_SMEM_BYTES (163840 + 2048)

__device__ __forceinline__ void gather_direct(
    const int* __restrict__ src_idx, const int* __restrict__ dst_idx,
    int e0, char* a_hi, char* a_lo, int tid)
{
    const float4* hs4 = (const float4*)g_hs;
    const float4* hd4 = (const float4*)g_hd;
#pragma unroll 4
    for (int it = 0; it < 16; ++it) {
        int idx = it * 256 + tid;
        int r = idx >> 5, c4 = idx & 31;
        int e = e0 + r;
        int si = __ldg(&src_idx[e]);
        int di = __ldg(&dst_idx[e]);
        float4 u = hs4[si * 32 + c4];
        float4 v = hd4[di * 32 + c4];
        float t0 = lrelu(u.x + v.x), t1 = lrelu(u.y + v.y);
        float t2 = lrelu(u.z + v.z), t3 = lrelu(u.w + v.w);
        uint32_t hi01, lo01, hi23, lo23;
        split2h(t0, t1, hi01, lo01);
        split2h(t2, t3, hi23, lo23);
        uint32_t off = swz_off(r, c4 * 4) * 2;
        *(uint2*)(a_hi + off) = make_uint2(hi01, hi23);
        *(uint2*)(a_lo + off) = make_uint2(lo01, lo23);
    }
}

__global__ __launch_bounds__(256, 1)
void edge_score_mma(const int* __restrict__ src_idx, const int* __restrict__ dst_idx,
                    const float* __restrict__ Wa1, const float* __restrict__ ba1,
                    const float* __restrict__ Wa2, const float* __restrict__ ba2)
{
    extern __shared__ float smem[];
    char* smc = (char*)smem;
    char* sW = smc;                    // 32KB (W_a1 fp16)
    char* sA_base = smc + 32768;       // 2 bufs x (hi 32KB + lo 32KB)
    float* sb1 = (float*)(smc + 163840);
    float* sw2 = (float*)(smc + 164352);
    float* sRed = (float*)(smc + 164864);  // 128 x 2

    const int tid = threadIdx.x;
    const int wid = tid >> 5;
    const int lane = tid & 31;

    for (int i = tid; i < D * D; i += 256) {
        int k = i >> 7, n = i & 127;
        ((__half*)sW)[swz_off(k, n)] = __float2half_rn(Wa1[i]);
    }
    if (tid < 128) { sb1[tid] = ba1[tid]; sw2[tid] = Wa2[tid]; }

    const float bias2 = ba2[0];
    const int rg = wid & 3, cg = wid >> 2;
    const int row_lo = (lane & 7) + ((lane >> 3) & 1) * 8;
    const int acg = (lane >> 4) & 1;
    const int x7 = lane & 7;
    const int g = lane >> 2;
    const int tig = lane & 3;
    const uint32_t sW_b = smem_u32(sW);
    const uint32_t sA_b = smem_u32(sA_base);

    const float4* hs4 = (const float4*)g_hs;
    const float4* hd4 = (const float4*)g_hd;

    const int bid = blockIdx.x;
    const int grid = gridDim.x;

    if (bid < NTILES)
        gather_direct(src_idx, dst_idx, bid * 128, sA_base, sA_base + 32768, tid);
    __syncthreads();

    const int c4 = tid & 31;
    const int rsub = tid >> 5;

    int buf = 0;
    for (int tile = bid; tile < NTILES; tile += grid) {
        const int nxt = tile + grid;
        const uint32_t cur_hi = sA_b + (uint32_t)buf * 65536u;
        const uint32_t cur_lo = cur_hi + 32768u;
        char* nxt_hi = sA_base + (buf ^ 1) * 65536;
        char* nxt_lo = nxt_hi + 32768;
        const bool have_nxt = (nxt < NTILES);
        const int ne0 = nxt * 128;

        float acc[2][8][4];
#pragma unroll
        for (int rc = 0; rc < 2; ++rc)
#pragma unroll
            for (int np = 0; np < 8; ++np)
#pragma unroll
                for (int j = 0; j < 4; ++j) acc[rc][np][j] = 0.f;

#pragma unroll
        for (int c = 0; c < 4; ++c) {
            // L: next tile's loads into registers
            float4 pu[4], pv[4];
            if (have_nxt) {
#pragma unroll
                for (int q = 0; q < 4; ++q) {
                    int r = c * 32 + q * 8 + rsub;
                    int e = ne0 + r;
                    int si = __ldg(&src_idx[e]);
                    int di = __ldg(&dst_idx[e]);
                    pu[q] = hs4[si * 32 + c4];
                    pv[q] = hd4[di * 32 + c4];
                }
            }

            // M: 2 k-steps of MMA on current buffer
#pragma unroll
            for (int ksi = 0; ksi < 2; ++ksi) {
                const int ks = 2 * c + ksi;
                uint32_t ah[2][4], al[2][4];
#pragma unroll
                for (int rc = 0; rc < 2; ++rc) {
                    uint32_t a_off = (uint32_t)((rg * 32 + rc * 16 + row_lo) << 8)
                                   + (uint32_t)((((2 * ks + acg) ^ x7) << 4));
                    LDSM_X4(ah[rc][0], ah[rc][1], ah[rc][2], ah[rc][3], cur_hi + a_off);
                    LDSM_X4(al[rc][0], al[rc][1], al[rc][2], al[rc][3], cur_lo + a_off);
                }
                const int bk = ks * 16 + row_lo;
#pragma unroll
                for (int p = 0; p < 4; ++p) {
                    int cidx = 2 * (cg * 4 + p) + acg;
                    uint32_t b_off = (uint32_t)(bk << 8) + (uint32_t)(((cidx ^ x7) << 4));
                    uint32_t bh0, bh1, bh2, bh3;
                    LDSM_X4_T(bh0, bh1, bh2, bh3, sW_b + b_off);
#pragma unroll
                    for (int rc = 0; rc < 2; ++rc) {
                        float* c0 = acc[rc][2 * p];
                        float* c1 = acc[rc][2 * p + 1];
                        MMA_F16(c0[0], c0[1], c0[2], c0[3], ah[rc][0], ah[rc][1], ah[rc][2], ah[rc][3], bh0, bh1);
                        MMA_F16(c0[0], c0[1], c0[2], c0[3], al[rc][0], al[rc][1], al[rc][2], al[rc][3], bh0, bh1);
                        MMA_F16(c1[0], c1[1], c1[2], c1[3], ah[rc][0], ah[rc][1], ah[rc][2], ah[rc][3], bh2, bh3);
                        MMA_F16(c1[0], c1[1], c1[2], c1[3], al[rc][0], al[rc][1], al[rc][2], al[rc][3], bh2, bh3);
                    }
                }
            }

            // S: convert + store next tile chunk
            if (have_nxt) {
#pragma unroll
                for (int q = 0; q < 4; ++q) {
                    int r = c * 32 + q * 8 + rsub;
                    float t0 = lrelu(pu[q].x + pv[q].x), t1 = lrelu(pu[q].y + pv[q].y);
                    float t2 = lrelu(pu[q].z + pv[q].z), t3 = lrelu(pu[q].w + pv[q].w);
                    uint32_t hi01, lo01, hi23, lo23;
                    split2h(t0, t1, hi01, lo01);
                    split2h(t2, t3, hi23, lo23);
                    uint32_t off = swz_off(r, c4 * 4) * 2;
                    *(uint2*)(nxt_hi + off) = make_uint2(hi01, hi23);
                    *(uint2*)(nxt_lo + off) = make_uint2(lo01, lo23);
                }
            }
        }

        // epilogue
#pragma unroll
        for (int rc = 0; rc < 2; ++rc) {
            float p0 = 0.f, p1 = 0.f;
#pragma unroll
            for (int np = 0; np < 8; ++np) {
                int n = cg * 64 + np * 8 + tig * 2;
                float b0 = sb1[n], b1 = sb1[n + 1];
                float w0 = sw2[n], w1 = sw2[n + 1];
                p0 += lrelu(acc[rc][np][0] + b0) * w0 + lrelu(acc[rc][np][1] + b1) * w1;
                p1 += lrelu(acc[rc][np][2] + b0) * w0 + lrelu(acc[rc][np][3] + b1) * w1;
            }
            p0 += __shfl_xor_sync(0xffffffffu, p0, 1);
            p0 += __shfl_xor_sync(0xffffffffu, p0, 2);
            p1 += __shfl_xor_sync(0xffffffffu, p1, 1);
            p1 += __shfl_xor_sync(0xffffffffu, p1, 2);
            if (tig == 0) {
                int row = rg * 32 + rc * 16 + g;
                sRed[row * 2 + cg] = p0;
                sRed[(row + 8) * 2 + cg] = p1;
            }
        }
        __syncthreads();
        if (tid < 128) {
            int slot = __ldg(&g_epos[tile * 128 + tid]);
            g_score[slot] = sRed[tid * 2] + sRed[tid * 2 + 1] + bias2;
        }
        __syncthreads();
        buf ^= 1;
    }
}

// ---------------- CSR build ----------------
__global__ void k_zero()
{
    int i = blockIdx.x * 256 + threadIdx.x;
    if (i < NDST) { g_count[i] = 0; g_cursor[i] = 0; }
}

__global__ void k_hist(const int* __restrict__ dst_idx)
{
    int e = blockIdx.x * 256 + threadIdx.x;
    if (e < NEDGE) atomicAdd(&g_count[dst_idx[e]], 1);
}

__global__ void k_scan1()
{
    int tid = threadIdx.x;
    int gid = blockIdx.x * 1024 + tid;
    int v = (gid < NDST) ? g_count[gid] : 0;
    int lane = tid & 31, w = tid >> 5;
    int x = v;
#pragma unroll
    for (int o = 1; o < 32; o <<= 1) {
        int y = __shfl_up_sync(0xffffffffu, x, o);
        if (lane >= o) x += y;
    }
    __shared__ int ws[32];
    if (lane == 31) ws[w] = x;
    __syncthreads();
    if (w == 0) {
        int y = ws[lane];
#pragma unroll
        for (int o = 1; o < 32; o <<= 1) {
            int z = __shfl_up_sync(0xffffffffu, y, o);
            if (lane >= o) y += z;
        }
        ws[lane] = y;
    }
    __syncthreads();
    int pref = (w > 0) ? ws[w - 1] : 0;
    int incl = x + pref;
    if (gid < NDST) g_offset[gid] = incl - v;
    if (tid == 1023) g_bsums[blockIdx.x] = incl;
}

__global__ void k_scan2(int nblocks)
{
    int tid = threadIdx.x;
    int v = (tid < nblocks) ? g_bsums[tid] : 0;
    int lane = tid & 31, w = tid >> 5;
    int x = v;
#pragma unroll
    for (int o = 1; o < 32; o <<= 1) {
        int y = __shfl_up_sync(0xffffffffu, x, o);
        if (lane >= o) x += y;
    }
    __shared__ int ws[2];
    if (lane == 31) ws[w] = x;
    __syncthreads();
    if (w == 1) x += ws[0];
    g_bsums2[tid] = x - v;
}

__global__ void k_scan3()
{
    int gid = blockIdx.x * 1024 + threadIdx.x;
    if (gid < NDST) g_offset[gid] += g_bsums2[blockIdx.x];
    if (gid == 0) g_offset[NDST] = NEDGE;
}

__global__ void k_scatter(const int* __restrict__ dst_idx, const int* __restrict__ src_idx)
{
    int e = blockIdx.x * 256 + threadIdx.x;
    if (e < NEDGE) {
        int d = dst_idx[e];
        int p = atomicAdd(&g_cursor[d], 1);
        int slot = g_offset[d] + p;
        g_epos[e] = slot;
        g_srcp[slot] = src_idx[e];
    }
}

// ---------------- softmax + aggregate ----------------
__global__ void k_aggregate()
{
    int gw = (blockIdx.x * blockDim.x + threadIdx.x) >> 5;
    int lane = threadIdx.x & 31;
    if (gw >= NDST) return;
    int beg = g_offset[gw], end = g_offset[gw + 1];

    const float4* hs4 = (const float4*)g_hs;
    const float4* hd4 = (const float4*)g_hd;
    float4 acc = make_float4(0.f, 0.f, 0.f, 0.f);

    if (end > beg) {
        float m = __int_as_float(0xff800000);
        for (int i = beg + lane; i < end; i += 32)
            m = fmaxf(m, g_score[i]);
#pragma unroll
        for (int o = 16; o; o >>= 1) m = fmaxf(m, __shfl_xor_sync(0xffffffffu, m, o));

        float dsum = 0.f;
        for (int i = beg + lane; i < end; i += 32)
            dsum += __expf(g_score[i] - m);
#pragma unroll
        for (int o = 16; o; o >>= 1) dsum += __shfl_xor_sync(0xffffffffu, dsum, o);
        float inv = 1.f / dsum;

        int s_nx = g_srcp[beg];
        float sc_nx = g_score[beg];
        for (int i = beg; i < end; ++i) {
            int s = s_nx;
            float sc = sc_nx;
            if (i + 1 < end) { s_nx = g_srcp[i + 1]; sc_nx = g_score[i + 1]; }
            float w = __expf(sc - m) * inv;
            float4 h = hs4[s * 32 + lane];
            acc.x += w * h.x; acc.y += w * h.y; acc.z += w * h.z; acc.w += w * h.w;
        }
        float4 hv = hd4[gw * 32 + lane];
        acc.x += hv.x; acc.y += hv.y; acc.z += hv.z; acc.w += hv.w;
    }
    ((float4*)g_nf)[gw * 32 + lane] = acc;
}

// ---------------- launch ----------------
extern "C" void kernel_launch(void* const* d_in, const int* in_sizes, int n_in,
                              void* d_out, int out_size)
{
    const float* feat_src = (const float*)d_in[0];
    const float* feat_dst = (const float*)d_in[1];
    const int*   src_idx  = (const int*)d_in[2];
    const int*   dst_idx  = (const int*)d_in[3];
    const float* W_src = (const float*)d_in[4];
    const float* b_src = (const float*)d_in[5];
    const float* W_dst = (const float*)d_in[6];
    const float* b_dst = (const float*)d_in[7];
    const float* W_a1  = (const float*)d_in[8];
    const float* b_a1  = (const float*)d_in[9];
    const float* W_a2  = (const float*)d_in[10];
    const float* b_a2  = (const float*)d_in[11];
    const float* W_out = (const float*)d_in[12];
    const float* b_out = (const float*)d_in[13];
    float* out = (float*)d_out;

    float *hs_p, *hd_p, *nf_p;
    cudaGetSymbolAddress((void**)&hs_p, g_hs);
    cudaGetSymbolAddress((void**)&hd_p, g_hd);
    cudaGetSymbolAddress((void**)&nf_p, g_nf);

    int nsm = 148;
    cudaDeviceGetAttribute(&nsm, cudaDevAttrMultiProcessorCount, 0);
    if (nsm <= 0 || nsm > NTILES) nsm = 148;

    cudaFuncSetAttribute(gemm_node_tc, cudaFuncAttributeMaxDynamicSharedMemorySize, GN_SMEM);
    cudaFuncSetAttribute(gemm_node_dual, cudaFuncAttributeMaxDynamicSharedMemorySize, GN_SMEM);
    cudaFuncSetAttribute(edge_score_mma, cudaFuncAttributeMaxDynamicSharedMemorySize, ES_SMEM_BYTES);

    const int gemm_blocks = (NSRC + 127) / 128;
    const int scan_blocks = (NDST + 1023) / 1024;

    // 1. fused node projections (2-term fp16 HMMA, 2 CTAs/SM)
    gemm_node_dual<<<2 * gemm_blocks, 256, GN_SMEM>>>(
        feat_src, W_src, b_src, hs_p,
        feat_dst, W_dst, b_dst, hd_p, NSRC, gemm_blocks);

    // 2. CSR build
    k_zero<<<(NDST + 255) / 256, 256>>>();
    k_hist<<<(NEDGE + 255) / 256, 256>>>(dst_idx);
    k_scan1<<<scan_blocks, 1024>>>();
    k_scan2<<<1, 64>>>(scan_blocks);
    k_scan3<<<scan_blocks, 1024>>>();
    k_scatter<<<(NEDGE + 255) / 256, 256>>>(dst_idx, src_idx);

    // 3. per-edge attention scores (2-term fp16 HMMA, persistent)
    edge_score_mma<<<nsm, 256, ES_SMEM_BYTES>>>(src_idx, dst_idx, W_a1, b_a1, W_a2, b_a2);

    // 4. segment softmax + weighted aggregation
    k_aggregate<<<(NDST * 32 + 255) / 256, 256>>>();

    // 5. output projection + leaky relu -> d_out
    gemm_node_tc<<<gemm_blocks, 256, GN_SMEM>>>(nf_p, W_out, b_out, out, NDST, 1);
}

// round 14
// speedup vs baseline: 2.4774x; 1.1160x over previous
#include <cuda_runtime.h>
#include <cuda_fp16.h>
#include <cstdint>

#define D 128
#define NSRC 50000
#define NDST 50000
#define NEDGE 640000
#define NTILES (NEDGE / 128)
#define NEG_SLOPE 0.01f

// ---------------- device scratch (static, no allocation) ----------------
__device__ float g_hs[NSRC * D];
__device__ float g_hd[NDST * D];
__device__ float g_nf[NDST * D];
__device__ float g_score[NEDGE];   // CSR-permuted scores
__device__ int g_srcp[NEDGE];      // CSR-permuted src indices
__device__ int g_epos[NEDGE];      // edge -> CSR slot
__device__ int g_count[NDST];
__device__ int g_offset[NDST + 1];
__device__ int g_cursor[NDST];
__device__ int g_bsums[64];
__device__ int g_bsums2[64];

__device__ __forceinline__ float lrelu(float x) { return x > 0.f ? x : NEG_SLOPE * x; }

// Swizzled element offset inside a [128 rows x 128 cols] f16 tile.
__device__ __forceinline__ uint32_t swz_off(int r, int c) {
    return (uint32_t)((r << 7) + ((((c >> 3) ^ (r & 7)) << 3) + (c & 7)));
}

__device__ __forceinline__ uint32_t smem_u32(const void* p) {
    uint32_t a;
    asm("{ .reg .u64 t; cvta.to.shared.u64 t, %1; cvt.u32.u64 %0, t; }" : "=r"(a) : "l"(p));
    return a;
}

#define LDSM_X4(r0, r1, r2, r3, addr) \
    asm volatile("ldmatrix.sync.aligned.m8n8.x4.shared.b16 {%0,%1,%2,%3}, [%4];" \
        : "=r"(r0), "=r"(r1), "=r"(r2), "=r"(r3) : "r"(addr))
#define LDSM_X4_T(r0, r1, r2, r3, addr) \
    asm volatile("ldmatrix.sync.aligned.m8n8.x4.trans.shared.b16 {%0,%1,%2,%3}, [%4];" \
        : "=r"(r0), "=r"(r1), "=r"(r2), "=r"(r3) : "r"(addr))
#define MMA_F16(c0, c1, c2, c3, a0, a1, a2, a3, b0, b1) \
    asm volatile("mma.sync.aligned.m16n8k16.row.col.f32.f16.f16.f32 " \
        "{%0,%1,%2,%3}, {%4,%5,%6,%7}, {%8,%9}, {%0,%1,%2,%3};" \
        : "+f"(c0), "+f"(c1), "+f"(c2), "+f"(c3) \
        : "r"(a0), "r"(a1), "r"(a2), "r"(a3), "r"(b0), "r"(b1))

// split two fp32 into fp16 hi pair + fp16 residual pair (packed f16x2 words)
__device__ __forceinline__ void split2h(float t0, float t1, uint32_t& hi, uint32_t& lo) {
    __half2 h = __floats2half2_rn(t0, t1);
    float h0 = __low2float(h), h1 = __high2float(h);
    __half2 l = __floats2half2_rn(t0 - h0, t1 - h1);
    hi = *reinterpret_cast<uint32_t*>(&h);
    lo = *reinterpret_cast<uint32_t*>(&l);
}

// =======================================================================
// Node GEMM via HMMA (2-term fp16: A hi+lo, W single fp16) — proven.
// =======================================================================
#define GN_SMEM (96 * 1024 + 512)

__device__ __forceinline__ void gemm_node_body(
    const float* __restrict__ A, const float* __restrict__ W,
    const float* __restrict__ bias, float* __restrict__ Out,
    int nrows, int act, int blk, char* smc)
{
    char* sW    = smc;
    char* sA_hi = smc + 32768;
    char* sA_lo = smc + 65536;
    float* sbias = (float*)(smc + 98304);

    const int tid = threadIdx.x;
    const int wid = tid >> 5;
    const int lane = tid & 31;
    const int row0 = blk * 128;

    for (int i = tid; i < D * D; i += 256) {
        int k = i >> 7, n = i & 127;
        ((__half*)sW)[swz_off(k, n)] = __float2half_rn(W[i]);
    }
    {
        const float4* A4 = (const float4*)A;
#pragma unroll 4
        for (int it = 0; it < 16; ++it) {
            int idx = it * 256 + tid;
            int r = idx >> 5, c4 = idx & 31;
            int gr = row0 + r;
            float4 v = make_float4(0.f, 0.f, 0.f, 0.f);
            if (gr < nrows) v = A4[gr * 32 + c4];
            uint32_t hi01, lo01, hi23, lo23;
            split2h(v.x, v.y, hi01, lo01);
            split2h(v.z, v.w, hi23, lo23);
            uint32_t off = swz_off(r, c4 * 4) * 2;
            *(uint2*)(sA_hi + off) = make_uint2(hi01, hi23);
            *(uint2*)(sA_lo + off) = make_uint2(lo01, lo23);
        }
    }
    if (tid < 128) sbias[tid] = bias[tid];
    __syncthreads();

    const int rg = wid & 3, cg = wid >> 2;
    const int row_lo = (lane & 7) + ((lane >> 3) & 1) * 8;
    const int acg = (lane >> 4) & 1;
    const int x7 = lane & 7;
    const int g = lane >> 2;
    const int tig = lane & 3;
    const uint32_t sA_hi_b = smem_u32(sA_hi);
    const uint32_t sA_lo_b = smem_u32(sA_lo);
    const uint32_t sW_b = smem_u32(sW);

    float acc[2][8][4];
#pragma unroll
    for (int rc = 0; rc < 2; ++rc)
#pragma unroll
        for (int np = 0; np < 8; ++np)
#pragma unroll
            for (int j = 0; j < 4; ++j) acc[rc][np][j] = 0.f;

#pragma unroll
    for (int ks = 0; ks < 8; ++ks) {
        uint32_t ah[2][4], al[2][4];
#pragma unroll
        for (int rc = 0; rc < 2; ++rc) {
            uint32_t a_off = (uint32_t)((rg * 32 + rc * 16 + row_lo) << 8)
                           + (uint32_t)((((2 * ks + acg) ^ x7) << 4));
            LDSM_X4(ah[rc][0], ah[rc][1], ah[rc][2], ah[rc][3], sA_hi_b + a_off);
            LDSM_X4(al[rc][0], al[rc][1], al[rc][2], al[rc][3], sA_lo_b + a_off);
        }
        const int bk = ks * 16 + row_lo;
#pragma unroll
        for (int p = 0; p < 4; ++p) {
            int cidx = 2 * (cg * 4 + p) + acg;
            uint32_t b_off = (uint32_t)(bk << 8) + (uint32_t)(((cidx ^ x7) << 4));
            uint32_t bh0, bh1, bh2, bh3;
            LDSM_X4_T(bh0, bh1, bh2, bh3, sW_b + b_off);
#pragma unroll
            for (int rc = 0; rc < 2; ++rc) {
                float* c0 = acc[rc][2 * p];
                float* c1 = acc[rc][2 * p + 1];
                MMA_F16(c0[0], c0[1], c0[2], c0[3], ah[rc][0], ah[rc][1], ah[rc][2], ah[rc][3], bh0, bh1);
                MMA_F16(c0[0], c0[1], c0[2], c0[3], al[rc][0], al[rc][1], al[rc][2], al[rc][3], bh0, bh1);
                MMA_F16(c1[0], c1[1], c1[2], c1[3], ah[rc][0], ah[rc][1], ah[rc][2], ah[rc][3], bh2, bh3);
                MMA_F16(c1[0], c1[1], c1[2], c1[3], al[rc][0], al[rc][1], al[rc][2], al[rc][3], bh2, bh3);
            }
        }
    }

#pragma unroll
    for (int rc = 0; rc < 2; ++rc) {
#pragma unroll
        for (int np = 0; np < 8; ++np) {
            int n = cg * 64 + np * 8 + tig * 2;
            float b0 = sbias[n], b1 = sbias[n + 1];
            int r1 = row0 + rg * 32 + rc * 16 + g;
            float v0 = acc[rc][np][0] + b0, v1 = acc[rc][np][1] + b1;
            float v2 = acc[rc][np][2] + b0, v3 = acc[rc][np][3] + b1;
            if (act) { v0 = lrelu(v0); v1 = lrelu(v1); v2 = lrelu(v2); v3 = lrelu(v3); }
            if (r1 < nrows) *(float2*)(Out + r1 * 128 + n) = make_float2(v0, v1);
            if (r1 + 8 < nrows) *(float2*)(Out + (r1 + 8) * 128 + n) = make_float2(v2, v3);
        }
    }
}

__global__ __launch_bounds__(256, 2)
void gemm_node_tc(const float* __restrict__ A, const float* __restrict__ W,
                  const float* __restrict__ bias, float* __restrict__ Out,
                  int nrows, int act)
{
    extern __shared__ float smem[];
    gemm_node_body(A, W, bias, Out, nrows, act, blockIdx.x, (char*)smem);
}

__global__ __launch_bounds__(256, 2)
void gemm_node_dual(const float* __restrict__ A0, const float* __restrict__ W0,
                    const float* __restrict__ b0, float* __restrict__ O0,
                    const float* __restrict__ A1, const float* __restrict__ W1,
                    const float* __restrict__ b1, float* __restrict__ O1,
                    int nrows, int nb)
{
    extern __shared__ float smem[];
    if (blockIdx.x < nb)
        gemm_node_body(A0, W0, b0, O0, nrows, 0, blockIdx.x, (char*)smem);
    else
        gemm_node_body(A1, W1, b1, O1, nrows, 0, blockIdx.x - nb, (char*)smem);
}

// =======================================================================
// Edge scoring: warp-specialized. 512 threads.
//   warps 0-7  = consumers: LDSM + HMMA + epilogue on buffer `buf`
//   warps 8-15 = producers: gather tile t+grid into buffer `buf^1`
// One __syncthreads per tile = full/empty exchange.
// SMEM: sW 32KB | sA 2 x (hi 32KB + lo 32KB) | sb1 | sw2 | sRed = 165888
// =======================================================================
#define ES_SMEM_BYTES 165888

// producer gather: 256 threads, each handles 8 (edge, 8-col-group) cells
__device__ __forceinline__ void gather_ws(
    const int* __restrict__ src_idx, const int* __restrict__ dst_idx,
    int e0, char* a_hi, char* a_lo, int tid2)
{
    const float4* hs4 = (const float4*)g_hs;
    const float4* hd4 = (const float4*)g_hd;
#pragma unroll
    for (int it = 0; it < 8; ++it) {
        int idx = it * 256 + tid2;
        int r = idx >> 4;          // edge row 0..127
        int c8 = idx & 15;         // 8-col group 0..15
        int e = e0 + r;
        int si = __ldg(&src_idx[e]);
        int di = __ldg(&dst_idx[e]);
        float4 u0 = hs4[si * 32 + c8 * 2];
        float4 u1 = hs4[si * 32 + c8 * 2 + 1];
        float4 v0 = hd4[di * 32 + c8 * 2];
        float4 v1 = hd4[di * 32 + c8 * 2 + 1];
        float t0 = lrelu(u0.x + v0.x), t1 = lrelu(u0.y + v0.y);
        float t2 = lrelu(u0.z + v0.z), t3 = lrelu(u0.w + v0.w);
        float t4 = lrelu(u1.x + v1.x), t5 = lrelu(u1.y + v1.y);
        float t6 = lrelu(u1.z + v1.z), t7 = lrelu(u1.w + v1.w);
        uint4 hi, lo;
        split2h(t0, t1, hi.x, lo.x);
        split2h(t2, t3, hi.y, lo.y);
        split2h(t4, t5, hi.z, lo.z);
        split2h(t6, t7, hi.w, lo.w);
        uint32_t off = swz_off(r, c8 * 8) * 2;   // 16B-aligned
        *(uint4*)(a_hi + off) = hi;
        *(uint4*)(a_lo + off) = lo;
    }
}

__global__ __launch_bounds__(512, 1)
void edge_score_mma(const int* __restrict__ src_idx, const int* __restrict__ dst_idx,
                    const float* __restrict__ Wa1, const float* __restrict__ ba1,
                    const float* __restrict__ Wa2, const float* __restrict__ ba2)
{
    extern __shared__ float smem[];
    char* smc = (char*)smem;
    char* sW = smc;                    // 32KB (W_a1 fp16)
    char* sA_base = smc + 32768;       // 2 bufs x (hi 32KB + lo 32KB)
    float* sb1 = (float*)(smc + 163840);
    float* sw2 = (float*)(smc + 164352);
    float* sRed = (float*)(smc + 164864);  // 128 x 2

    const int tid = threadIdx.x;
    const int wid = tid >> 5;
    const int lane = tid & 31;
    const bool consumer = (wid < 8);

    for (int i = tid; i < D * D; i += 512) {
        int k = i >> 7, n = i & 127;
        ((__half*)sW)[swz_off(k, n)] = __float2half_rn(Wa1[i]);
    }
    if (tid < 128) { sb1[tid] = ba1[tid]; sw2[tid] = Wa2[tid]; }

    const float bias2 = ba2[0];
    const int rg = wid & 3, cg = wid >> 2;           // consumer tiling (wid 0-7)
    const int row_lo = (lane & 7) + ((lane >> 3) & 1) * 8;
    const int acg = (lane >> 4) & 1;
    const int x7 = lane & 7;
    const int g = lane >> 2;
    const int tig = lane & 3;
    const uint32_t sW_b = smem_u32(sW);
    const uint32_t sA_b = smem_u32(sA_base);
    const int tid2 = tid - 256;                      // producer index

    const int bid = blockIdx.x;
    const int grid = gridDim.x;

    // prologue: producers fill buffer 0 with first tile
    if (!consumer && bid < NTILES)
        gather_ws(src_idx, dst_idx, bid * 128, sA_base, sA_base + 32768, tid2);
    __syncthreads();

    int buf = 0;
    for (int tile = bid; tile < NTILES; tile += grid) {
        if (consumer) {
            const uint32_t cur_hi = sA_b + (uint32_t)buf * 65536u;
            const uint32_t cur_lo = cur_hi + 32768u;

            float acc[2][8][4];
#pragma unroll
            for (int rc = 0; rc < 2; ++rc)
#pragma unroll
                for (int np = 0; np < 8; ++np)
#pragma unroll
                    for (int j = 0; j < 4; ++j) acc[rc][np][j] = 0.f;

#pragma unroll
            for (int ks = 0; ks < 8; ++ks) {
                uint32_t ah[2][4], al[2][4];
#pragma unroll
                for (int rc = 0; rc < 2; ++rc) {
                    uint32_t a_off = (uint32_t)((rg * 32 + rc * 16 + row_lo) << 8)
                                   + (uint32_t)((((2 * ks + acg) ^ x7) << 4));
                    LDSM_X4(ah[rc][0], ah[rc][1], ah[rc][2], ah[rc][3], cur_hi + a_off);
                    LDSM_X4(al[rc][0], al[rc][1], al[rc][2], al[rc][3], cur_lo + a_off);
                }
                const int bk = ks * 16 + row_lo;
#pragma unroll
                for (int p = 0; p < 4; ++p) {
                    int cidx = 2 * (cg * 4 + p) + acg;
                    uint32_t b_off = (uint32_t)(bk << 8) + (uint32_t)(((cidx ^ x7) << 4));
                    uint32_t bh0, bh1, bh2, bh3;
                    LDSM_X4_T(bh0, bh1, bh2, bh3, sW_b + b_off);
#pragma unroll
                    for (int rc = 0; rc < 2; ++rc) {
                        float* c0 = acc[rc][2 * p];
                        float* c1 = acc[rc][2 * p + 1];
                        MMA_F16(c0[0], c0[1], c0[2], c0[3], ah[rc][0], ah[rc][1], ah[rc][2], ah[rc][3], bh0, bh1);
                        MMA_F16(c0[0], c0[1], c0[2], c0[3], al[rc][0], al[rc][1], al[rc][2], al[rc][3], bh0, bh1);
                        MMA_F16(c1[0], c1[1], c1[2], c1[3], ah[rc][0], ah[rc][1], ah[rc][2], ah[rc][3], bh2, bh3);
                        MMA_F16(c1[0], c1[1], c1[2], c1[3], al[rc][0], al[rc][1], al[rc][2], al[rc][3], bh2, bh3);
                    }
                }
            }

            // epilogue: per-warp partial dot over its 64 cols
#pragma unroll
            for (int rc = 0; rc < 2; ++rc) {
                float p0 = 0.f, p1 = 0.f;
#pragma unroll
                for (int np = 0; np < 8; ++np) {
                    int n = cg * 64 + np * 8 + tig * 2;
                    float b0 = sb1[n], b1 = sb1[n + 1];
                    float w0 = sw2[n], w1 = sw2[n + 1];
                    p0 += lrelu(acc[rc][np][0] + b0) * w0 + lrelu(acc[rc][np][1] + b1) * w1;
                    p1 += lrelu(acc[rc][np][2] + b0) * w0 + lrelu(acc[rc][np][3] + b1) * w1;
                }
                p0 += __shfl_xor_sync(0xffffffffu, p0, 1);
                p0 += __shfl_xor_sync(0xffffffffu, p0, 2);
                p1 += __shfl_xor_sync(0xffffffffu, p1, 1);
                p1 += __shfl_xor_sync(0xffffffffu, p1, 2);
                if (tig == 0) {
                    int row = rg * 32 + rc * 16 + g;
                    sRed[row * 2 + cg] = p0;
                    sRed[(row + 8) * 2 + cg] = p1;
                }
            }
            asm volatile("bar.sync 1, 256;" ::: "memory");   // consumers only
            if (tid < 128) {
                int slot = __ldg(&g_epos[tile * 128 + tid]);
                g_score[slot] = sRed[tid * 2] + sRed[tid * 2 + 1] + bias2;
            }
        } else {
            // producers: gather next tile into the other buffer
            const int nxt = tile + grid;
            if (nxt < NTILES) {
                char* nxt_hi = sA_base + (buf ^ 1) * 65536;
                gather_ws(src_idx, dst_idx, nxt * 128, nxt_hi, nxt_hi + 32768, tid2);
            }
        }
        __syncthreads();   // buffer exchange: nxt full, cur free, sRed consumed
        buf ^= 1;
    }
}

// ---------------- CSR build ----------------
__global__ void k_zero()
{
    int i = blockIdx.x * 256 + threadIdx.x;
    if (i < NDST) { g_count[i] = 0; g_cursor[i] = 0; }
}

__global__ void k_hist(const int* __restrict__ dst_idx)
{
    int e = blockIdx.x * 256 + threadIdx.x;
    if (e < NEDGE) atomicAdd(&g_count[dst_idx[e]], 1);
}

__global__ void k_scan1()
{
    int tid = threadIdx.x;
    int gid = blockIdx.x * 1024 + tid;
    int v = (gid < NDST) ? g_count[gid] : 0;
    int lane = tid & 31, w = tid >> 5;
    int x = v;
#pragma unroll
    for (int o = 1; o < 32; o <<= 1) {
        int y = __shfl_up_sync(0xffffffffu, x, o);
        if (lane >= o) x += y;
    }
    __shared__ int ws[32];
    if (lane == 31) ws[w] = x;
    __syncthreads();
    if (w == 0) {
        int y = ws[lane];
#pragma unroll
        for (int o = 1; o < 32; o <<= 1) {
            int z = __shfl_up_sync(0xffffffffu, y, o);
            if (lane >= o) y += z;
        }
        ws[lane] = y;
    }
    __syncthreads();
    int pref = (w > 0) ? ws[w - 1] : 0;
    int incl = x + pref;
    if (gid < NDST) g_offset[gid] = incl - v;
    if (tid == 1023) g_bsums[blockIdx.x] = incl;
}

__global__ void k_scan2(int nblocks)
{
    int tid = threadIdx.x;
    int v = (tid < nblocks) ? g_bsums[tid] : 0;
    int lane = tid & 31, w = tid >> 5;
    int x = v;
#pragma unroll
    for (int o = 1; o < 32; o <<= 1) {
        int y = __shfl_up_sync(0xffffffffu, x, o);
        if (lane >= o) x += y;
    }
    __shared__ int ws[2];
    if (lane == 31) ws[w] = x;
    __syncthreads();
    if (w == 1) x += ws[0];
    g_bsums2[tid] = x - v;
}

__global__ void k_scan3()
{
    int gid = blockIdx.x * 1024 + threadIdx.x;
    if (gid < NDST) g_offset[gid] += g_bsums2[blockIdx.x];
    if (gid == 0) g_offset[NDST] = NEDGE;
}

__global__ void k_scatter(const int* __restrict__ dst_idx, const int* __restrict__ src_idx)
{
    int e = blockIdx.x * 256 + threadIdx.x;
    if (e < NEDGE) {
        int d = dst_idx[e];
        int p = atomicAdd(&g_cursor[d], 1);
        int slot = g_offset[d] + p;
        g_epos[e] = slot;
        g_srcp[slot] = src_idx[e];
    }
}

// ---------------- softmax + aggregate ----------------
__global__ void k_aggregate()
{
    int gw = (blockIdx.x * blockDim.x + threadIdx.x) >> 5;
    int lane = threadIdx.x & 31;
    if (gw >= NDST) return;
    int beg = g_offset[gw], end = g_offset[gw + 1];

    const float4* hs4 = (const float4*)g_hs;
    const float4* hd4 = (const float4*)g_hd;
    float4 acc = make_float4(0.f, 0.f, 0.f, 0.f);

    if (end > beg) {
        float m = __int_as_float(0xff800000);
        for (int i = beg + lane; i < end; i += 32)
            m = fmaxf(m, g_score[i]);
#pragma unroll
        for (int o = 16; o; o >>= 1) m = fmaxf(m, __shfl_xor_sync(0xffffffffu, m, o));

        float dsum = 0.f;
        for (int i = beg + lane; i < end; i += 32)
            dsum += __expf(g_score[i] - m);
#pragma unroll
        for (int o = 16; o; o >>= 1) dsum += __shfl_xor_sync(0xffffffffu, dsum, o);
        float inv = 1.f / dsum;

        int s_nx = g_srcp[beg];
        float sc_nx = g_score[beg];
        for (int i = beg; i < end; ++i) {
            int s = s_nx;
            float sc = sc_nx;
            if (i + 1 < end) { s_nx = g_srcp[i + 1]; sc_nx = g_score[i + 1]; }
            float w = __expf(sc - m) * inv;
            float4 h = hs4[s * 32 + lane];
            acc.x += w * h.x; acc.y += w * h.y; acc.z += w * h.z; acc.w += w * h.w;
        }
        float4 hv = hd4[gw * 32 + lane];
        acc.x += hv.x; acc.y += hv.y; acc.z += hv.z; acc.w += hv.w;
    }
    ((float4*)g_nf)[gw * 32 + lane] = acc;
}

// ---------------- launch ----------------
extern "C" void kernel_launch(void* const* d_in, const int* in_sizes, int n_in,
                              void* d_out, int out_size)
{
    const float* feat_src = (const float*)d_in[0];
    const float* feat_dst = (const float*)d_in[1];
    const int*   src_idx  = (const int*)d_in[2];
    const int*   dst_idx  = (const int*)d_in[3];
    const float* W_src = (const float*)d_in[4];
    const float* b_src = (const float*)d_in[5];
    const float* W_dst = (const float*)d_in[6];
    const float* b_dst = (const float*)d_in[7];
    const float* W_a1  = (const float*)d_in[8];
    const float* b_a1  = (const float*)d_in[9];
    const float* W_a2  = (const float*)d_in[10];
    const float* b_a2  = (const float*)d_in[11];
    const float* W_out = (const float*)d_in[12];
    const float* b_out = (const float*)d_in[13];
    float* out = (float*)d_out;

    float *hs_p, *hd_p, *nf_p;
    cudaGetSymbolAddress((void**)&hs_p, g_hs);
    cudaGetSymbolAddress((void**)&hd_p, g_hd);
    cudaGetSymbolAddress((void**)&nf_p, g_nf);

    int nsm = 148;
    cudaDeviceGetAttribute(&nsm, cudaDevAttrMultiProcessorCount, 0);
    if (nsm <= 0 || nsm > NTILES) nsm = 148;

    cudaFuncSetAttribute(gemm_node_tc, cudaFuncAttributeMaxDynamicSharedMemorySize, GN_SMEM);
    cudaFuncSetAttribute(gemm_node_dual, cudaFuncAttributeMaxDynamicSharedMemorySize, GN_SMEM);
    cudaFuncSetAttribute(edge_score_mma, cudaFuncAttributeMaxDynamicSharedMemorySize, ES_SMEM_BYTES);

    const int gemm_blocks = (NSRC + 127) / 128;
    const int scan_blocks = (NDST + 1023) / 1024;

    // 1. fused node projections
    gemm_node_dual<<<2 * gemm_blocks, 256, GN_SMEM>>>(
        feat_src, W_src, b_src, hs_p,
        feat_dst, W_dst, b_dst, hd_p, NSRC, gemm_blocks);

    // 2. CSR build
    k_zero<<<(NDST + 255) / 256, 256>>>();
    k_hist<<<(NEDGE + 255) / 256, 256>>>(dst_idx);
    k_scan1<<<scan_blocks, 1024>>>();
    k_scan2<<<1, 64>>>(scan_blocks);
    k_scan3<<<scan_blocks, 1024>>>();
    k_scatter<<<(NEDGE + 255) / 256, 256>>>(dst_idx, src_idx);

    // 3. per-edge attention scores (warp-specialized HMMA)
    edge_score_mma<<<nsm, 512, ES_SMEM_BYTES>>>(src_idx, dst_idx, W_a1, b_a1, W_a2, b_a2);

    // 4. segment softmax + weighted aggregation
    k_aggregate<<<(NDST * 32 + 255) / 256, 256>>>();

    // 5. output projection + leaky relu -> d_out
    gemm_node_tc<<<gemm_blocks, 256, GN_SMEM>>>(nf_p, W_out, b_out, out, NDST, 1);
}

// round 15
// speedup vs baseline: 2.6125x; 1.0545x over previous
#include <cuda_runtime.h>
#include <cuda_fp16.h>
#include <cstdint>

#define D 128
#define NSRC 50000
#define NDST 50000
#define NEDGE 640000
#define NTILES (NEDGE / 128)
#define NEG_SLOPE 0.01f

// ---------------- device scratch (static, no allocation) ----------------
__device__ float g_hs[NSRC * D];
__device__ float g_hd[NDST * D];
__device__ float g_nf[NDST * D];
__device__ float g_score[NEDGE];   // CSR-ordered scores
__device__ int g_srcp[NEDGE];      // CSR-ordered src indices
__device__ int g_dstp[NEDGE];      // CSR-ordered dst indices
__device__ int g_count[NDST];
__device__ int g_offset[NDST + 1];
__device__ int g_cursor[NDST];
__device__ int g_bsums[64];
__device__ int g_bsums2[64];

__device__ __forceinline__ float lrelu(float x) { return x > 0.f ? x : NEG_SLOPE * x; }

// Swizzled element offset inside a [128 rows x 128 cols] f16 tile.
__device__ __forceinline__ uint32_t swz_off(int r, int c) {
    return (uint32_t)((r << 7) + ((((c >> 3) ^ (r & 7)) << 3) + (c & 7)));
}

__device__ __forceinline__ uint32_t smem_u32(const void* p) {
    uint32_t a;
    asm("{ .reg .u64 t; cvta.to.shared.u64 t, %1; cvt.u32.u64 %0, t; }" : "=r"(a) : "l"(p));
    return a;
}

#define LDSM_X4(r0, r1, r2, r3, addr) \
    asm volatile("ldmatrix.sync.aligned.m8n8.x4.shared.b16 {%0,%1,%2,%3}, [%4];" \
        : "=r"(r0), "=r"(r1), "=r"(r2), "=r"(r3) : "r"(addr))
#define LDSM_X4_T(r0, r1, r2, r3, addr) \
    asm volatile("ldmatrix.sync.aligned.m8n8.x4.trans.shared.b16 {%0,%1,%2,%3}, [%4];" \
        : "=r"(r0), "=r"(r1), "=r"(r2), "=r"(r3) : "r"(addr))
#define MMA_F16(c0, c1, c2, c3, a0, a1, a2, a3, b0, b1) \
    asm volatile("mma.sync.aligned.m16n8k16.row.col.f32.f16.f16.f32 " \
        "{%0,%1,%2,%3}, {%4,%5,%6,%7}, {%8,%9}, {%0,%1,%2,%3};" \
        : "+f"(c0), "+f"(c1), "+f"(c2), "+f"(c3) \
        : "r"(a0), "r"(a1), "r"(a2), "r"(a3), "r"(b0), "r"(b1))

// split two fp32 into fp16 hi pair + fp16 residual pair (packed f16x2 words)
__device__ __forceinline__ void split2h(float t0, float t1, uint32_t& hi, uint32_t& lo) {
    __half2 h = __floats2half2_rn(t0, t1);
    float h0 = __low2float(h), h1 = __high2float(h);
    __half2 l = __floats2half2_rn(t0 - h0, t1 - h1);
    hi = *reinterpret_cast<uint32_t*>(&h);
    lo = *reinterpret_cast<uint32_t*>(&l);
}

// =======================================================================
// Node GEMM via HMMA (2-term fp16: A hi+lo, W single fp16) — proven.
// =======================================================================
#define GN_SMEM (96 * 1024 + 512)

__device__ __forceinline__ void gemm_node_body(
    const float* __restrict__ A, const float* __restrict__ W,
    const float* __restrict__ bias, float* __restrict__ Out,
    int nrows, int act, int blk, char* smc)
{
    char* sW    = smc;
    char* sA_hi = smc + 32768;
    char* sA_lo = smc + 65536;
    float* sbias = (float*)(smc + 98304);

    const int tid = threadIdx.x;
    const int wid = tid >> 5;
    const int lane = tid & 31;
    const int row0 = blk * 128;

    for (int i = tid; i < D * D; i += 256) {
        int k = i >> 7, n = i & 127;
        ((__half*)sW)[swz_off(k, n)] = __float2half_rn(W[i]);
    }
    {
        const float4* A4 = (const float4*)A;
#pragma unroll 4
        for (int it = 0; it < 16; ++it) {
            int idx = it * 256 + tid;
            int r = idx >> 5, c4 = idx & 31;
            int gr = row0 + r;
            float4 v = make_float4(0.f, 0.f, 0.f, 0.f);
            if (gr < nrows) v = A4[gr * 32 + c4];
            uint32_t hi01, lo01, hi23, lo23;
            split2h(v.x, v.y, hi01, lo01);
            split2h(v.z, v.w, hi23, lo23);
            uint32_t off = swz_off(r, c4 * 4) * 2;
            *(uint2*)(sA_hi + off) = make_uint2(hi01, hi23);
            *(uint2*)(sA_lo + off) = make_uint2(lo01, lo23);
        }
    }
    if (tid < 128) sbias[tid] = bias[tid];
    __syncthreads();

    const int rg = wid & 3, cg = wid >> 2;
    const int row_lo = (lane & 7) + ((lane >> 3) & 1) * 8;
    const int acg = (lane >> 4) & 1;
    const int x7 = lane & 7;
    const int g = lane >> 2;
    const int tig = lane & 3;
    const uint32_t sA_hi_b = smem_u32(sA_hi);
    const uint32_t sA_lo_b = smem_u32(sA_lo);
    const uint32_t sW_b = smem_u32(sW);

    float acc[2][8][4];
#pragma unroll
    for (int rc = 0; rc < 2; ++rc)
#pragma unroll
        for (int np = 0; np < 8; ++np)
#pragma unroll
            for (int j = 0; j < 4; ++j) acc[rc][np][j] = 0.f;

#pragma unroll
    for (int ks = 0; ks < 8; ++ks) {
        uint32_t ah[2][4], al[2][4];
#pragma unroll
        for (int rc = 0; rc < 2; ++rc) {
            uint32_t a_off = (uint32_t)((rg * 32 + rc * 16 + row_lo) << 8)
                           + (uint32_t)((((2 * ks + acg) ^ x7) << 4));
            LDSM_X4(ah[rc][0], ah[rc][1], ah[rc][2], ah[rc][3], sA_hi_b + a_off);
            LDSM_X4(al[rc][0], al[rc][1], al[rc][2], al[rc][3], sA_lo_b + a_off);
        }
        const int bk = ks * 16 + row_lo;
#pragma unroll
        for (int p = 0; p < 4; ++p) {
            int cidx = 2 * (cg * 4 + p) + acg;
            uint32_t b_off = (uint32_t)(bk << 8) + (uint32_t)(((cidx ^ x7) << 4));
            uint32_t bh0, bh1, bh2, bh3;
            LDSM_X4_T(bh0, bh1, bh2, bh3, sW_b + b_off);
#pragma unroll
            for (int rc = 0; rc < 2; ++rc) {
                float* c0 = acc[rc][2 * p];
                float* c1 = acc[rc][2 * p + 1];
                MMA_F16(c0[0], c0[1], c0[2], c0[3], ah[rc][0], ah[rc][1], ah[rc][2], ah[rc][3], bh0, bh1);
                MMA_F16(c0[0], c0[1], c0[2], c0[3], al[rc][0], al[rc][1], al[rc][2], al[rc][3], bh0, bh1);
                MMA_F16(c1[0], c1[1], c1[2], c1[3], ah[rc][0], ah[rc][1], ah[rc][2], ah[rc][3], bh2, bh3);
                MMA_F16(c1[0], c1[1], c1[2], c1[3], al[rc][0], al[rc][1], al[rc][2], al[rc][3], bh2, bh3);
            }
        }
    }

#pragma unroll
    for (int rc = 0; rc < 2; ++rc) {
#pragma unroll
        for (int np = 0; np < 8; ++np) {
            int n = cg * 64 + np * 8 + tig * 2;
            float b0 = sbias[n], b1 = sbias[n + 1];
            int r1 = row0 + rg * 32 + rc * 16 + g;
            float v0 = acc[rc][np][0] + b0, v1 = acc[rc][np][1] + b1;
            float v2 = acc[rc][np][2] + b0, v3 = acc[rc][np][3] + b1;
            if (act) { v0 = lrelu(v0); v1 = lrelu(v1); v2 = lrelu(v2); v3 = lrelu(v3); }
            if (r1 < nrows) *(float2*)(Out + r1 * 128 + n) = make_float2(v0, v1);
            if (r1 + 8 < nrows) *(float2*)(Out + (r1 + 8) * 128 + n) = make_float2(v2, v3);
        }
    }
}

__global__ __launch_bounds__(256, 2)
void gemm_node_tc(const float* __restrict__ A, const float* __restrict__ W,
                  const float* __restrict__ bias, float* __restrict__ Out,
                  int nrows, int act)
{
    extern __shared__ float smem[];
    gemm_node_body(A, W, bias, Out, nrows, act, blockIdx.x, (char*)smem);
}

__global__ __launch_bounds__(256, 2)
void gemm_node_dual(const float* __restrict__ A0, const float* __restrict__ W0,
                    const float* __restrict__ b0, float* __restrict__ O0,
                    const float* __restrict__ A1, const float* __restrict__ W1,
                    const float* __restrict__ b1, float* __restrict__ O1,
                    int nrows, int nb)
{
    extern __shared__ float smem[];
    if (blockIdx.x < nb)
        gemm_node_body(A0, W0, b0, O0, nrows, 0, blockIdx.x, (char*)smem);
    else
        gemm_node_body(A1, W1, b1, O1, nrows, 0, blockIdx.x - nb, (char*)smem);
}

// =======================================================================
// Edge scoring: warp-specialized, CSR-ordered tiles.
//   warps 0-7  = consumers: LDSM + HMMA + epilogue on buffer `buf`
//   warps 8-15 = producers: gather CSR tile t+grid (srcp/dstp, MLP-16)
// dst-sorted order => hd gathers L1-hit; score stores contiguous.
// =======================================================================
#define ES_SMEM_BYTES 165888

__device__ __forceinline__ void gather_csr(int e0, char* a_hi, char* a_lo, int tid2)
{
    const float4* hs4 = (const float4*)g_hs;
    const float4* hd4 = (const float4*)g_hd;
    const int rbase = tid2 >> 4;   // 0..15
    const int c8 = tid2 & 15;      // 8-col group

#pragma unroll
    for (int half = 0; half < 2; ++half) {
        int rr[4], sis[4], dis[4];
#pragma unroll
        for (int q = 0; q < 4; ++q) {
            rr[q] = (half * 4 + q) * 16 + rbase;
            int slot = e0 + rr[q];
            sis[q] = __ldg(&g_srcp[slot]);
            dis[q] = __ldg(&g_dstp[slot]);
        }
        float4 u0[4], u1[4], v0[4], v1[4];
#pragma unroll
        for (int q = 0; q < 4; ++q) {
            u0[q] = hs4[sis[q] * 32 + c8 * 2];
            u1[q] = hs4[sis[q] * 32 + c8 * 2 + 1];
            v0[q] = hd4[dis[q] * 32 + c8 * 2];
            v1[q] = hd4[dis[q] * 32 + c8 * 2 + 1];
        }
#pragma unroll
        for (int q = 0; q < 4; ++q) {
            float t0 = lrelu(u0[q].x + v0[q].x), t1 = lrelu(u0[q].y + v0[q].y);
            float t2 = lrelu(u0[q].z + v0[q].z), t3 = lrelu(u0[q].w + v0[q].w);
            float t4 = lrelu(u1[q].x + v1[q].x), t5 = lrelu(u1[q].y + v1[q].y);
            float t6 = lrelu(u1[q].z + v1[q].z), t7 = lrelu(u1[q].w + v1[q].w);
            uint4 hi, lo;
            split2h(t0, t1, hi.x, lo.x);
            split2h(t2, t3, hi.y, lo.y);
            split2h(t4, t5, hi.z, lo.z);
            split2h(t6, t7, hi.w, lo.w);
            uint32_t off = swz_off(rr[q], c8 * 8) * 2;   // 16B-aligned
            *(uint4*)(a_hi + off) = hi;
            *(uint4*)(a_lo + off) = lo;
        }
    }
}

__global__ __launch_bounds__(512, 1)
void edge_score_mma(const float* __restrict__ Wa1, const float* __restrict__ ba1,
                    const float* __restrict__ Wa2, const float* __restrict__ ba2)
{
    extern __shared__ float smem[];
    char* smc = (char*)smem;
    char* sW = smc;                    // 32KB (W_a1 fp16)
    char* sA_base = smc + 32768;       // 2 bufs x (hi 32KB + lo 32KB)
    float* sb1 = (float*)(smc + 163840);
    float* sw2 = (float*)(smc + 164352);
    float* sRed = (float*)(smc + 164864);  // 128 x 2

    const int tid = threadIdx.x;
    const int wid = tid >> 5;
    const int lane = tid & 31;
    const bool consumer = (wid < 8);

    for (int i = tid; i < D * D; i += 512) {
        int k = i >> 7, n = i & 127;
        ((__half*)sW)[swz_off(k, n)] = __float2half_rn(Wa1[i]);
    }
    if (tid < 128) { sb1[tid] = ba1[tid]; sw2[tid] = Wa2[tid]; }

    const float bias2 = ba2[0];
    const int rg = wid & 3, cg = wid >> 2;
    const int row_lo = (lane & 7) + ((lane >> 3) & 1) * 8;
    const int acg = (lane >> 4) & 1;
    const int x7 = lane & 7;
    const int g = lane >> 2;
    const int tig = lane & 3;
    const uint32_t sW_b = smem_u32(sW);
    const uint32_t sA_b = smem_u32(sA_base);
    const int tid2 = tid - 256;

    const int bid = blockIdx.x;
    const int grid = gridDim.x;

    // prologue: producers fill buffer 0 with first tile
    if (!consumer && bid < NTILES)
        gather_csr(bid * 128, sA_base, sA_base + 32768, tid2);
    __syncthreads();

    int buf = 0;
    for (int tile = bid; tile < NTILES; tile += grid) {
        if (consumer) {
            const uint32_t cur_hi = sA_b + (uint32_t)buf * 65536u;
            const uint32_t cur_lo = cur_hi + 32768u;

            float acc[2][8][4];
#pragma unroll
            for (int rc = 0; rc < 2; ++rc)
#pragma unroll
                for (int np = 0; np < 8; ++np)
#pragma unroll
                    for (int j = 0; j < 4; ++j) acc[rc][np][j] = 0.f;

#pragma unroll
            for (int ks = 0; ks < 8; ++ks) {
                uint32_t ah[2][4], al[2][4];
#pragma unroll
                for (int rc = 0; rc < 2; ++rc) {
                    uint32_t a_off = (uint32_t)((rg * 32 + rc * 16 + row_lo) << 8)
                                   + (uint32_t)((((2 * ks + acg) ^ x7) << 4));
                    LDSM_X4(ah[rc][0], ah[rc][1], ah[rc][2], ah[rc][3], cur_hi + a_off);
                    LDSM_X4(al[rc][0], al[rc][1], al[rc][2], al[rc][3], cur_lo + a_off);
                }
                const int bk = ks * 16 + row_lo;
#pragma unroll
                for (int p = 0; p < 4; ++p) {
                    int cidx = 2 * (cg * 4 + p) + acg;
                    uint32_t b_off = (uint32_t)(bk << 8) + (uint32_t)(((cidx ^ x7) << 4));
                    uint32_t bh0, bh1, bh2, bh3;
                    LDSM_X4_T(bh0, bh1, bh2, bh3, sW_b + b_off);
#pragma unroll
                    for (int rc = 0; rc < 2; ++rc) {
                        float* c0 = acc[rc][2 * p];
                        float* c1 = acc[rc][2 * p + 1];
                        MMA_F16(c0[0], c0[1], c0[2], c0[3], ah[rc][0], ah[rc][1], ah[rc][2], ah[rc][3], bh0, bh1);
                        MMA_F16(c0[0], c0[1], c0[2], c0[3], al[rc][0], al[rc][1], al[rc][2], al[rc][3], bh0, bh1);
                        MMA_F16(c1[0], c1[1], c1[2], c1[3], ah[rc][0], ah[rc][1], ah[rc][2], ah[rc][3], bh2, bh3);
                        MMA_F16(c1[0], c1[1], c1[2], c1[3], al[rc][0], al[rc][1], al[rc][2], al[rc][3], bh2, bh3);
                    }
                }
            }

            // epilogue
#pragma unroll
            for (int rc = 0; rc < 2; ++rc) {
                float p0 = 0.f, p1 = 0.f;
#pragma unroll
                for (int np = 0; np < 8; ++np) {
                    int n = cg * 64 + np * 8 + tig * 2;
                    float b0 = sb1[n], b1 = sb1[n + 1];
                    float w0 = sw2[n], w1 = sw2[n + 1];
                    p0 += lrelu(acc[rc][np][0] + b0) * w0 + lrelu(acc[rc][np][1] + b1) * w1;
                    p1 += lrelu(acc[rc][np][2] + b0) * w0 + lrelu(acc[rc][np][3] + b1) * w1;
                }
                p0 += __shfl_xor_sync(0xffffffffu, p0, 1);
                p0 += __shfl_xor_sync(0xffffffffu, p0, 2);
                p1 += __shfl_xor_sync(0xffffffffu, p1, 1);
                p1 += __shfl_xor_sync(0xffffffffu, p1, 2);
                if (tig == 0) {
                    int row = rg * 32 + rc * 16 + g;
                    sRed[row * 2 + cg] = p0;
                    sRed[(row + 8) * 2 + cg] = p1;
                }
            }
            asm volatile("bar.sync 1, 256;" ::: "memory");   // consumers only
            if (tid < 128)
                g_score[tile * 128 + tid] = sRed[tid * 2] + sRed[tid * 2 + 1] + bias2;
        } else {
            const int nxt = tile + grid;
            if (nxt < NTILES) {
                char* nxt_hi = sA_base + (buf ^ 1) * 65536;
                gather_csr(nxt * 128, nxt_hi, nxt_hi + 32768, tid2);
            }
        }
        __syncthreads();   // buffer exchange
        buf ^= 1;
    }
}

// ---------------- CSR build ----------------
__global__ void k_zero()
{
    int i = blockIdx.x * 256 + threadIdx.x;
    if (i < NDST) { g_count[i] = 0; g_cursor[i] = 0; }
}

__global__ void k_hist(const int* __restrict__ dst_idx)
{
    int e = blockIdx.x * 256 + threadIdx.x;
    if (e < NEDGE) atomicAdd(&g_count[dst_idx[e]], 1);
}

__global__ void k_scan1()
{
    int tid = threadIdx.x;
    int gid = blockIdx.x * 1024 + tid;
    int v = (gid < NDST) ? g_count[gid] : 0;
    int lane = tid & 31, w = tid >> 5;
    int x = v;
#pragma unroll
    for (int o = 1; o < 32; o <<= 1) {
        int y = __shfl_up_sync(0xffffffffu, x, o);
        if (lane >= o) x += y;
    }
    __shared__ int ws[32];
    if (lane == 31) ws[w] = x;
    __syncthreads();
    if (w == 0) {
        int y = ws[lane];
#pragma unroll
        for (int o = 1; o < 32; o <<= 1) {
            int z = __shfl_up_sync(0xffffffffu, y, o);
            if (lane >= o) y += z;
        }
        ws[lane] = y;
    }
    __syncthreads();
    int pref = (w > 0) ? ws[w - 1] : 0;
    int incl = x + pref;
    if (gid < NDST) g_offset[gid] = incl - v;
    if (tid == 1023) g_bsums[blockIdx.x] = incl;
}

__global__ void k_scan2(int nblocks)
{
    int tid = threadIdx.x;
    int v = (tid < nblocks) ? g_bsums[tid] : 0;
    int lane = tid & 31, w = tid >> 5;
    int x = v;
#pragma unroll
    for (int o = 1; o < 32; o <<= 1) {
        int y = __shfl_up_sync(0xffffffffu, x, o);
        if (lane >= o) x += y;
    }
    __shared__ int ws[2];
    if (lane == 31) ws[w] = x;
    __syncthreads();
    if (w == 1) x += ws[0];
    g_bsums2[tid] = x - v;
}

__global__ void k_scan3()
{
    int gid = blockIdx.x * 1024 + threadIdx.x;
    if (gid < NDST) g_offset[gid] += g_bsums2[blockIdx.x];
    if (gid == 0) g_offset[NDST] = NEDGE;
}

__global__ void k_scatter(const int* __restrict__ dst_idx, const int* __restrict__ src_idx)
{
    int e = blockIdx.x * 256 + threadIdx.x;
    if (e < NEDGE) {
        int d = dst_idx[e];
        int p = atomicAdd(&g_cursor[d], 1);
        int slot = g_offset[d] + p;
        g_srcp[slot] = src_idx[e];
        g_dstp[slot] = d;
    }
}

// ---------------- softmax + aggregate ----------------
__global__ void k_aggregate()
{
    int gw = (blockIdx.x * blockDim.x + threadIdx.x) >> 5;
    int lane = threadIdx.x & 31;
    if (gw >= NDST) return;
    int beg = g_offset[gw], end = g_offset[gw + 1];

    const float4* hs4 = (const float4*)g_hs;
    const float4* hd4 = (const float4*)g_hd;
    float4 acc = make_float4(0.f, 0.f, 0.f, 0.f);

    if (end > beg) {
        float m = __int_as_float(0xff800000);
        for (int i = beg + lane; i < end; i += 32)
            m = fmaxf(m, g_score[i]);
#pragma unroll
        for (int o = 16; o; o >>= 1) m = fmaxf(m, __shfl_xor_sync(0xffffffffu, m, o));

        float dsum = 0.f;
        for (int i = beg + lane; i < end; i += 32)
            dsum += __expf(g_score[i] - m);
#pragma unroll
        for (int o = 16; o; o >>= 1) dsum += __shfl_xor_sync(0xffffffffu, dsum, o);
        float inv = 1.f / dsum;

        int s_nx = g_srcp[beg];
        float sc_nx = g_score[beg];
        for (int i = beg; i < end; ++i) {
            int s = s_nx;
            float sc = sc_nx;
            if (i + 1 < end) { s_nx = g_srcp[i + 1]; sc_nx = g_score[i + 1]; }
            float w = __expf(sc - m) * inv;
            float4 h = hs4[s * 32 + lane];
            acc.x += w * h.x; acc.y += w * h.y; acc.z += w * h.z; acc.w += w * h.w;
        }
        float4 hv = hd4[gw * 32 + lane];
        acc.x += hv.x; acc.y += hv.y; acc.z += hv.z; acc.w += hv.w;
    }
    ((float4*)g_nf)[gw * 32 + lane] = acc;
}

// ---------------- launch ----------------
extern "C" void kernel_launch(void* const* d_in, const int* in_sizes, int n_in,
                              void* d_out, int out_size)
{
    const float* feat_src = (const float*)d_in[0];
    const float* feat_dst = (const float*)d_in[1];
    const int*   src_idx  = (const int*)d_in[2];
    const int*   dst_idx  = (const int*)d_in[3];
    const float* W_src = (const float*)d_in[4];
    const float* b_src = (const float*)d_in[5];
    const float* W_dst = (const float*)d_in[6];
    const float* b_dst = (const float*)d_in[7];
    const float* W_a1  = (const float*)d_in[8];
    const float* b_a1  = (const float*)d_in[9];
    const float* W_a2  = (const float*)d_in[10];
    const float* b_a2  = (const float*)d_in[11];
    const float* W_out = (const float*)d_in[12];
    const float* b_out = (const float*)d_in[13];
    float* out = (float*)d_out;

    float *hs_p, *hd_p, *nf_p;
    cudaGetSymbolAddress((void**)&hs_p, g_hs);
    cudaGetSymbolAddress((void**)&hd_p, g_hd);
    cudaGetSymbolAddress((void**)&nf_p, g_nf);

    int nsm = 148;
    cudaDeviceGetAttribute(&nsm, cudaDevAttrMultiProcessorCount, 0);
    if (nsm <= 0 || nsm > NTILES) nsm = 148;

    cudaFuncSetAttribute(gemm_node_tc, cudaFuncAttributeMaxDynamicSharedMemorySize, GN_SMEM);
    cudaFuncSetAttribute(gemm_node_dual, cudaFuncAttributeMaxDynamicSharedMemorySize, GN_SMEM);
    cudaFuncSetAttribute(edge_score_mma, cudaFuncAttributeMaxDynamicSharedMemorySize, ES_SMEM_BYTES);

    const int gemm_blocks = (NSRC + 127) / 128;
    const int scan_blocks = (NDST + 1023) / 1024;

    // 1. fused node projections
    gemm_node_dual<<<2 * gemm_blocks, 256, GN_SMEM>>>(
        feat_src, W_src, b_src, hs_p,
        feat_dst, W_dst, b_dst, hd_p, NSRC, gemm_blocks);

    // 2. CSR build (produces g_srcp / g_dstp, CSR-sorted)
    k_zero<<<(NDST + 255) / 256, 256>>>();
    k_hist<<<(NEDGE + 255) / 256, 256>>>(dst_idx);
    k_scan1<<<scan_blocks, 1024>>>();
    k_scan2<<<1, 64>>>(scan_blocks);
    k_scan3<<<scan_blocks, 1024>>>();
    k_scatter<<<(NEDGE + 255) / 256, 256>>>(dst_idx, src_idx);

    // 3. per-edge attention scores (warp-specialized HMMA, CSR order)
    edge_score_mma<<<nsm, 512, ES_SMEM_BYTES>>>(W_a1, b_a1, W_a2, b_a2);

    // 4. segment softmax + weighted aggregation
    k_aggregate<<<(NDST * 32 + 255) / 256, 256>>>();

    // 5. output projection + leaky relu -> d_out
    gemm_node_tc<<<gemm_blocks, 256, GN_SMEM>>>(nf_p, W_out, b_out, out, NDST, 1);
}